// round 13
// baseline (speedup 1.0000x reference)
#include <cuda_runtime.h>
#include <cuda_bf16.h>
#include <math.h>
#define IC 256
typedef unsigned long long u64; typedef unsigned int u32;

__device__ __align__(256) float g_xs[22020096];
__device__ __align__(256) float g_px[3 * 1048576];
__device__ __align__(256) float g_part[2][86016];
__device__ __align__(256) float g_partx[8192];
__device__ __align__(256) float g_xc[1966080];
__device__ __align__(256) float g_wT[3][IC * 9 * IC];
__device__ __align__(256) float g_scale[3][3][IC];
__device__ __align__(256) float g_bias[3][3][IC];
__device__ int g_sel[3][4][512];
__device__ int g_cnt[4];
__device__ int g_rc[512];
// bf16 split planes, k-half interleaved: [split][b][c0p][cpl4][y][x][half]
__device__ __align__(256) u32 gF0b[2 * 8388608];
__device__ __align__(256) u32 gXsb[2 * 8388608];
// bf16 split weights: [(t*2+s)*9+tap][c0p][cpl4][n][half]
__device__ __align__(256) u32 gWb[2 * 2 * 9 * 16 * 2048];

__constant__ int f_st[10] = {1024, 1144, 1400, 2488, 2552, 2808, 2872, 2936, 3000, 3064};
__constant__ int f_typ[9] = {3, 0, 0, 4, 1, 2, 1, 2, 2};
__constant__ int f_lvl[9] = {0, 1, 2, 0, 1, 1, 2, 2, 0};
__constant__ int f_tX[9]  = {3, 4, 2, 2, 4, 2, 2, 2, 2};
__constant__ int f_gi[9]  = {-1, -1, -1, 3, 1, 1, 2, 2, 0};
__constant__ int f_gn[9]  = {0, 0, 0, 120, 256, 256, 64, 64, 1024};

__device__ __forceinline__ u64 pack2(float v) {
    u64 d; unsigned r = __float_as_uint(v);
    asm("mov.b64 %0, {%1, %2};" : "=l"(d) : "r"(r), "r"(r)); return d;
}
__device__ __forceinline__ u64 ffma2(u64 a, u64 b, u64 c) {
    u64 d; asm("fma.rn.f32x2 %0, %1, %2, %3;" : "=l"(d) : "l"(a), "l"(b), "l"(c)); return d;
}
__device__ __forceinline__ void unpack2(u64 v, float& lo, float& hi) {
    unsigned a, b; asm("mov.b64 {%0, %1}, %2;" : "=r"(a), "=r"(b) : "l"(v));
    lo = __uint_as_float(a); hi = __uint_as_float(b);
}
__device__ __forceinline__ float sigm(float x) { return 1.f / (1.f + expf(-x)); }
__device__ __forceinline__ u32 bfpair(float lo, float hi) {
    __nv_bfloat162 h = __floats2bfloat162_rn(lo, hi);
    return *(u32*)&h;
}
__device__ __forceinline__ float bfres(float v) {
    return v - __bfloat162float(__float2bfloat16(v));
}
__device__ __forceinline__ void mmab(float* c, const u32* a, const u32* b) {
    asm volatile("mma.sync.aligned.m16n8k16.row.col.f32.bf16.bf16.f32 "
        "{%0,%1,%2,%3}, {%4,%5,%6,%7}, {%8,%9}, {%0,%1,%2,%3};"
        : "+f"(c[0]), "+f"(c[1]), "+f"(c[2]), "+f"(c[3])
        : "r"(a[0]), "r"(a[1]), "r"(a[2]), "r"(a[3]), "r"(b[0]), "r"(b[1]));
}

struct PrepArgs { const float *w[3], *b[3], *g[3], *bb[3], *m[3], *v[3]; };

__global__ void prep_k(PrepArgs P) {
    int idx = blockIdx.x * blockDim.x + threadIdx.x;
    if (idx < 4) g_cnt[idx] = 0;
    if (idx < 512) g_rc[idx] = 0;
    if (idx < 9 * IC) {
        int t = idx / (3 * IC), rem = idx % (3 * IC), l = rem / IC, ch = rem % IC;
        float s = P.g[t][l * IC + ch] / sqrtf(P.v[t][l * IC + ch] + 1e-5f);
        g_scale[t][l][ch] = s;
        g_bias[t][l][ch] = P.bb[t][l * IC + ch] + (P.b[t][ch] - P.m[t][l * IC + ch]) * s;
    }
    int j = idx - 9 * IC;
    if (j >= 0 && j < 3 * IC * 9 * IC) {
        int t = j / (IC * 9 * IC), rem = j % (IC * 9 * IC);
        int ci = rem / (9 * IC), tap = (rem / IC) % 9, n = rem % IC;
        g_wT[t][ci * 9 * IC + tap * IC + n] = P.w[t][n * IC * 9 + ci * 9 + tap];
    }
    int j2 = j - 3 * IC * 9 * IC;
    if (j2 >= 0 && j2 < 2 * 9 * 32768) {
        int t = j2 / (9 * 32768), rem = j2 % (9 * 32768);
        int tap = rem / 32768, r2 = rem % 32768;
        int c0p = r2 >> 11, cpl = (r2 >> 8) & 7, n = r2 & 255;
        int cp = c0p * 8 + cpl;
        float w0 = P.w[t][(n * 256 + 2 * cp) * 9 + tap];
        float w1 = P.w[t][(n * 256 + 2 * cp + 1) * 9 + tap];
        size_t o = ((size_t)((t * 2) * 9 + tap) * 16 + c0p) * 2048 + (cpl & 3) * 512 + n * 2 + (cpl >> 2);
        gWb[o] = bfpair(w0, w1);
        gWb[o + (size_t)9 * 32768] = bfpair(bfres(w0), bfres(w1));
    }
}

__global__ void splitF_k(const float* __restrict__ f0) {
    int i = blockIdx.x * blockDim.x + threadIdx.x;
    if (i >= 8388608) return;
    int b = i >> 21, rem = i & 2097151;
    int cp = rem >> 14, yx = rem & 16383;
    float v0 = f0[((size_t)(b * 256 + 2 * cp) * 16384) + yx];
    float v1 = f0[((size_t)(b * 256 + 2 * cp + 1) * 16384) + yx];
    int c0p = cp >> 3, cpl = cp & 7;
    size_t o = ((((size_t)(b * 16 + c0p) * 4 + (cpl & 3)) << 14) + yx) * 2 + (cpl >> 2);
    gF0b[o] = bfpair(v0, v1);
    gF0b[o + 8388608] = bfpair(bfres(v0), bfres(v1));
}

__global__ void dummy_k() {}

// exact FFMA2 conv body (verbatim)
__device__ __forceinline__ void ffmaConv(float* sBuf, int tid,
    const float* __restrict__ src, int srcH, int srcW, int y0, int x0,
    const float* __restrict__ wT, int nblk, const float* sc, const float* bi,
    int om, float* outX, int outW, int outPS, float* outPart, int partW,
    float* outPx, const float* __restrict__ ehw)
{
    float* sIn = sBuf; float* sW = sBuf + 1520;
    const int cg = tid >> 4, sg = tid & 15;
    const int srow = sg >> 1, sx = (sg & 1) * 8;
    u64 acc[4][8];
#pragma unroll
    for (int ii = 0; ii < 4; ii++)
#pragma unroll
        for (int j = 0; j < 8; j++) acc[ii][j] = 0ull;
    for (int c0 = 0; c0 < IC; c0 += 8) {
        for (int e = tid; e < 1520; e += 256) {
            int ci = e / 190, rem = e % 190, r = rem / 19, cc = rem % 19;
            int gy = y0 - 1 + r, gx = x0 - 1 + cc;
            float v = 0.f;
            if (cc < 18 && gy >= 0 && gy < srcH && gx >= 0 && gx < srcW)
                v = src[((size_t)(c0 + ci) * srcH + gy) * srcW + gx];
            sIn[e] = v;
        }
        for (int e4 = tid; e4 < 2304; e4 += 256) {
            int ci = e4 / 288, rem = e4 % 288, tap = rem / 32, n4 = rem % 32;
            float4 v = *(const float4*)(wT + (size_t)(c0 + ci) * (9 * IC) + tap * IC + nblk * 128 + n4 * 4);
            *(float4*)(sW + ci * 1152 + tap * 128 + n4 * 4) = v;
        }
        __syncthreads();
#pragma unroll 1
        for (int ci = 0; ci < 8; ci++) {
#pragma unroll
            for (int dy = 0; dy < 3; dy++) {
                const float* rp = sIn + ci * 190 + (srow + dy) * 19 + sx;
                u64 rr[10];
#pragma unroll
                for (int j = 0; j < 10; j++) rr[j] = pack2(rp[j]);
                const u64* wp = (const u64*)(sW + ci * 1152 + dy * 384 + cg * 8);
#pragma unroll
                for (int dx = 0; dx < 3; dx++) {
                    u64 w0 = wp[dx * 64], w1 = wp[dx * 64 + 1], w2 = wp[dx * 64 + 2], w3 = wp[dx * 64 + 3];
#pragma unroll
                    for (int m = 0; m < 8; m++) {
                        acc[0][m] = ffma2(w0, rr[m + dx], acc[0][m]);
                        acc[1][m] = ffma2(w1, rr[m + dx], acc[1][m]);
                        acc[2][m] = ffma2(w2, rr[m + dx], acc[2][m]);
                        acc[3][m] = ffma2(w3, rr[m + dx], acc[3][m]);
                    }
                }
            }
        }
        __syncthreads();
    }
    float psum[8];
#pragma unroll
    for (int m = 0; m < 8; m++) psum[m] = 0.f;
    const int y = y0 + srow, xb = x0 + sx;
#pragma unroll
    for (int n2 = 0; n2 < 4; n2++) {
        int cha = nblk * 128 + cg * 8 + 2 * n2, chb = cha + 1;
        float sa = sc[cha], ta = bi[cha], sb = sc[chb], tb = bi[chb];
        float va[8], vb[8];
#pragma unroll
        for (int m = 0; m < 8; m++) {
            float lo, hi; unpack2(acc[n2][m], lo, hi);
            va[m] = fmaxf(fmaf(lo, sa, ta), 0.f);
            vb[m] = fmaxf(fmaf(hi, sb, tb), 0.f);
        }
        if (om == 0) {
            float* oa = outX + (size_t)cha * outPS + y * outW + xb;
            float* ob = outX + (size_t)chb * outPS + y * outW + xb;
            *(float4*)(oa) = make_float4(va[0], va[1], va[2], va[3]);
            *(float4*)(oa + 4) = make_float4(va[4], va[5], va[6], va[7]);
            *(float4*)(ob) = make_float4(vb[0], vb[1], vb[2], vb[3]);
            *(float4*)(ob + 4) = make_float4(vb[4], vb[5], vb[6], vb[7]);
        } else if (om == 1) {
            float wa = ehw[cha], wb = ehw[chb];
#pragma unroll
            for (int m = 0; m < 8; m++) psum[m] += va[m] * wa + vb[m] * wb;
        } else {
#pragma unroll
            for (int m = 0; m < 8; m++) {
                float* o = outPx + (size_t)(y * 32 + xb + m) * IC;
                o[cha] = va[m]; o[chb] = vb[m];
            }
        }
    }
    if (om == 1) {
#pragma unroll
        for (int m = 0; m < 8; m++) sW[cg * 128 + srow * 16 + sx + m] = psum[m];
        __syncthreads();
        if (tid < 128) {
            float a2 = 0.f;
#pragma unroll
            for (int c2 = 0; c2 < 16; c2++) a2 += sW[c2 * 128 + tid];
            outPart[(y0 + (tid >> 4)) * partW + x0 + (tid & 15)] = a2;
        }
    }
}

__global__ __launch_bounds__(256, 2)
void mega_k(const float* __restrict__ f0, const float* __restrict__ f1,
            const float* __restrict__ f2, const float* __restrict__ ehw) {
    __shared__ __align__(16) float sBuf[10752];
    const int tid = threadIdx.x, wid = tid >> 5, lane = tid & 31;
    const int bid = blockIdx.x;

    if (bid < 1024 || (bid >= 1464 && bid < 2488)) {
        // ===== bf16 2-split tensor conv lvl0, k-half-interleaved smem (LDS.64 fragments) =====
        const int tw = (bid >= 1464), i = tw ? bid - 1464 : bid;
        const int y = i >> 3, b = (i >> 1) & 3, nblk = i & 1;
        const int wx = wid & 3, wy = wid >> 2;
        u32* S = (u32*)sBuf;   // A: [2s][4cpl4][136px][2half] stride 280/cpl4, 1120/s ; B @2240: [2s][3dx]{1088}: [4cpl4][128n][2half] stride 264
        if (tw == 1) {
            if (tid == 0) {
                int lo = y > 0 ? y - 1 : 0, hi = y < 127 ? y + 1 : 127; long long gd = 0;
                for (int rr = lo; rr <= hi; rr++)
                    while (atomicAdd(&g_rc[b * 128 + rr], 0) < 2 && gd < 400000000LL) gd++;
            }
            __syncthreads(); __threadfence();
        }
        const u32* __restrict__ plane = tw ? gXsb : gF0b;
        float acc[16][4];
#pragma unroll
        for (int q = 0; q < 16; q++) { acc[q][0] = acc[q][1] = acc[q][2] = acc[q][3] = 0.f; }
        if (tid < 128) {   // zero halo px=128..135 (both halves)
            int s = tid >> 6, cpl4 = (tid >> 4) & 3, k = tid & 15;
            S[s * 1120 + cpl4 * 280 + 256 + k] = 0;
        }

        int dys[3]; int nd = 0;
#pragma unroll
        for (int dy = 0; dy < 3; dy++) { int iy = y + dy - 1; if (iy >= 0 && iy < 128) dys[nd++] = dy; }

        for (int di = 0; di < nd; di++) {
            int dy = dys[di], iy = y + dy - 1;
            for (int c0p = 0; c0p < 16; c0p++) {
                __syncthreads();
                for (int e = tid; e < 512; e += 256) {       // A stage uint4: (x,x+1)x(2half)
                    int s = e >= 256, r = e - s * 256;
                    int cpl4 = r >> 6, xh = r & 63;
                    uint4 v = *(const uint4*)(plane + (size_t)s * 8388608 +
                        (((size_t)((b * 16 + c0p) * 4 + cpl4) * 128 + iy) << 8) + xh * 4);
                    *(uint4*)(S + s * 1120 + cpl4 * 280 + xh * 4) = v;
                }
                for (int e = tid; e < 1536; e += 256) {      // B stage uint4: (n,n+1)x(2half)
                    int s = e >= 768, r = e - s * 768;
                    int dx = r >> 8, rr = r & 255, cpl4 = rr >> 6, ng = rr & 63;
                    const u32* src = gWb + ((size_t)((tw * 2 + s) * 9 + dy * 3 + dx) * 16 + c0p) * 2048
                                     + cpl4 * 512 + nblk * 256 + ng * 4;
                    *(uint4*)(S + 2240 + (s * 3 + dx) * 1088 + cpl4 * 264 + ng * 4) = *(const uint4*)src;
                }
                __syncthreads();
#pragma unroll
                for (int dx = 0; dx < 3; dx++) {
                    u32 a_[2][2][4];
#pragma unroll
                    for (int mf = 0; mf < 2; mf++) {
                        int px = wx * 32 + mf * 16 + (lane >> 2);
                        int g0 = px + dx - 1, g1 = g0 + 8;
                        int i0 = (g0 >= 0 && g0 < 128) ? g0 : 128;
                        int i1 = (g1 < 128) ? g1 : 128;
#pragma unroll
                        for (int s = 0; s < 2; s++) {
                            int base = s * 1120 + (lane & 3) * 280;
                            u64 v0 = *(const u64*)(S + base + i0 * 2);
                            u64 v1 = *(const u64*)(S + base + i1 * 2);
                            a_[s][mf][0] = (u32)v0; a_[s][mf][2] = (u32)(v0 >> 32);
                            a_[s][mf][1] = (u32)v1; a_[s][mf][3] = (u32)(v1 >> 32);
                        }
                    }
#pragma unroll
                    for (int nt = 0; nt < 8; nt++) {
                        int bb = 2240 + dx * 1088 + (lane & 3) * 264 + (wy * 64 + nt * 8 + (lane >> 2)) * 2;
                        u64 w0 = *(const u64*)(S + bb);
                        u64 w1 = *(const u64*)(S + bb + 3264);
                        u32 b0[2] = {(u32)w0, (u32)(w0 >> 32)};
                        u32 b1[2] = {(u32)w1, (u32)(w1 >> 32)};
#pragma unroll
                        for (int mf = 0; mf < 2; mf++) {
                            mmab(acc[mf * 8 + nt], a_[0][mf], b0);
                            mmab(acc[mf * 8 + nt], a_[0][mf], b1);
                            mmab(acc[mf * 8 + nt], a_[1][mf], b0);
                        }
                    }
                }
            }
        }
        const float* sc = g_scale[tw][0]; const float* bi = g_bias[tw][0];
        float psum[4] = {0.f, 0.f, 0.f, 0.f};
#pragma unroll
        for (int mf = 0; mf < 2; mf++)
#pragma unroll
            for (int nt = 0; nt < 8; nt++)
#pragma unroll
                for (int h = 0; h < 2; h++) {
                    int px = wx * 32 + mf * 16 + (lane >> 2) + h * 8;
                    int ch0 = nblk * 128 + wy * 64 + nt * 8 + (lane & 3) * 2;
                    float v0 = fmaxf(fmaf(acc[mf * 8 + nt][h * 2], sc[ch0], bi[ch0]), 0.f);
                    float v1 = fmaxf(fmaf(acc[mf * 8 + nt][h * 2 + 1], sc[ch0 + 1], bi[ch0 + 1]), 0.f);
                    if (tw == 0) {
                        size_t o = ((size_t)(b * 256 + ch0) * 128 + y) * 128 + px;
                        g_xs[o] = v0; g_xs[o + 16384] = v1;
                        int cp = ch0 >> 1, c0p = cp >> 3, cpl = cp & 7;
                        size_t ob = ((((size_t)((b * 16 + c0p) * 4 + (cpl & 3)) * 128 + y) * 128 + px)) * 2 + (cpl >> 2);
                        gXsb[ob] = bfpair(v0, v1);
                        gXsb[ob + 8388608] = bfpair(bfres(v0), bfres(v1));
                    } else psum[mf * 2 + h] += v0 * ehw[ch0] + v1 * ehw[ch0 + 1];
                }
        if (tw == 1) {
#pragma unroll
            for (int q = 0; q < 4; q++) {
                psum[q] += __shfl_xor_sync(0xffffffffu, psum[q], 1);
                psum[q] += __shfl_xor_sync(0xffffffffu, psum[q], 2);
            }
            __syncthreads();
            if ((lane & 3) == 0)
#pragma unroll
                for (int q = 0; q < 4; q++)
                    sBuf[wy * 128 + wx * 32 + (q & 1) * 8 + (q >> 1) * 16 + (lane >> 2)] = psum[q];
            __syncthreads();
            if (tid < 128) g_part[nblk][b * 16384 + y * 128 + tid] = sBuf[tid] + sBuf[128 + tid];
        } else {
            __threadfence(); __syncthreads();
            if (tid == 0) { atomicAdd(&g_rc[b * 128 + y], 1); atomicAdd(&g_cnt[0], 1); }
        }
        return;
    }

    // ===== FFMA2 segments (verbatim from passing R10) =====
    int s = 0; while (s < 9 && !(bid >= f_st[s] && bid < f_st[s + 1])) s++;
    const int typ = f_typ[s], lvl = f_lvl[s], tX = f_tX[s];
    const int i = bid - f_st[s];
    const int tile = i >> 3, b = (i >> 1) & 3, nblk = i & 1;
    const int y0 = (tile / tX) * 8, x0 = (tile % tX) * 16;
    if (f_gi[s] >= 0) {
        if (tid == 0) {
            long long gd = 0;
            while (atomicAdd(&g_cnt[f_gi[s]], 0) < f_gn[s] && gd < 400000000LL) gd++;
        }
        __syncthreads(); __threadfence();
    }
    const int Hs = (lvl == 0) ? 128 : ((lvl == 1) ? 64 : 32);
    const size_t xsoff = (lvl == 0) ? 0ul : ((lvl == 1) ? 16777216ul : 20971520ul);
    int tower = (typ == 0 || typ == 3) ? 0 : ((typ == 1 || typ == 4) ? 1 : 2);
    const float* sc = g_scale[tower][lvl];
    const float* bi = g_bias[tower][lvl];
    const float* wT = g_wT[tower];

    if (typ == 3) {
        ffmaConv(sBuf, tid, f0 + (size_t)b * IC * 16384, 128, 128, y0, x0, wT, nblk, sc, bi,
                 0, g_xc + (size_t)b * IC * 1920, 48, 1920, nullptr, 0, nullptr, ehw);
        __threadfence(); __syncthreads();
        if (tid == 0) atomicAdd(&g_cnt[3], 1);
    } else if (typ == 0) {
        const float* src = ((lvl == 1) ? f1 : f2) + (size_t)b * IC * Hs * Hs;
        ffmaConv(sBuf, tid, src, Hs, Hs, y0, x0, wT, nblk, sc, bi,
                 0, g_xs + xsoff + (size_t)b * IC * Hs * Hs, Hs, Hs * Hs, nullptr, 0, nullptr, ehw);
        __threadfence(); __syncthreads();
        if (tid == 0) atomicAdd(&g_cnt[lvl], 1);
    } else if (typ == 4) {
        ffmaConv(sBuf, tid, g_xc + (size_t)b * IC * 1920, 40, 48, y0, x0, wT, nblk, sc, bi,
                 1, nullptr, 0, 0, g_partx + nblk * 4096 + b * 1024, 32, nullptr, ehw);
    } else if (typ == 1) {
        int po = (lvl == 1) ? 65536 : 81920;
        ffmaConv(sBuf, tid, g_xs + xsoff + (size_t)b * IC * Hs * Hs, Hs, Hs, y0, x0, wT, nblk, sc, bi,
                 1, nullptr, 0, 0, g_part[nblk] + po + b * Hs * Hs, Hs, nullptr, ehw);
    } else {
        ffmaConv(sBuf, tid, g_xs + xsoff + (size_t)b * IC * Hs * Hs, Hs, Hs, y0, x0, wT, nblk, sc, bi,
                 2, nullptr, 0, 0, nullptr, 0, g_px + (size_t)lvl * 1048576 + (size_t)b * 1024 * IC, ehw);
    }
}

__global__ void em_k(const float* __restrict__ ehb, float* __restrict__ out) {
    int i = blockIdx.x * blockDim.x + threadIdx.x;
    if (i >= 86016) return;
    int emo = (i < 65536) ? 0 : ((i < 81920) ? 77824 - 65536 : 100352 - 81920);
    out[emo + i] = sigm(g_part[0][i] + g_part[1][i] + ehb[0]);
}

__global__ void sort_k(const int* __restrict__ coords, const float* __restrict__ base,
                       const float* __restrict__ ehb, float* __restrict__ out) {
    __shared__ u64 sk[1024];
    int lvl = blockIdx.x, b = blockIdx.y, t = threadIdx.x;
    int H = (lvl == 0) ? 128 : ((lvl == 1) ? 64 : 32);
    int nk = (lvl == 0) ? 512 : ((lvl == 1) ? 256 : 128);
    int emOff = (lvl == 0) ? 0 : ((lvl == 1) ? 77824 : 100352);
    int xyOff = (lvl == 0) ? 73728 : ((lvl == 1) ? 98304 : 106496);
    const float* em = base + emOff + b * H * H;
    for (int p = t; p < 1024; p += 512) {
        int r = coords[p], c = coords[1024 + p];
        float v = (lvl == 0) ? sigm(g_partx[b * 1024 + r * 32 + c] + g_partx[4096 + b * 1024 + r * 32 + c] + ehb[0])
                             : em[r * H + c];
        u64 key = ((u64)__float_as_uint(v) << 32) | (u32)(1023 - p);
        sk[p] = ~key;
    }
    __syncthreads();
    for (int k = 2; k <= 1024; k <<= 1)
        for (int j = k >> 1; j > 0; j >>= 1) {
            for (int i2 = t; i2 < 1024; i2 += 512) {
                int l = i2 ^ j;
                if (l > i2) {
                    u64 a = sk[i2], bb = sk[l];
                    if ((a > bb) == ((i2 & k) == 0)) { sk[i2] = bb; sk[l] = a; }
                }
            }
            __syncthreads();
        }
    if (t < nk) {
        int p = 1023 - (int)((~sk[t]) & 0xFFFFFFFFu);
        g_sel[lvl][b][t] = p;
        out[xyOff + (b * nk + t) * 2] = (float)coords[p];
        out[xyOff + (b * nk + t) * 2 + 1] = (float)coords[1024 + p];
    }
}

__global__ void head_k(const int* __restrict__ coords, const float* __restrict__ hw,
                       const float* __restrict__ hb, float* __restrict__ out) {
    int lvl = blockIdx.z, b = blockIdx.y;
    int nk = (lvl == 0) ? 512 : ((lvl == 1) ? 256 : 128);
    int finOff = (lvl == 0) ? 65536 : ((lvl == 1) ? 94208 : 104448);
    int k = blockIdx.x * 4 + (threadIdx.x >> 5), lane = threadIdx.x & 31;
    if (k >= nk) return;
    int p = g_sel[lvl][b][k];
    int r = coords[p], c = coords[1024 + p];
    const float* af = g_px + (size_t)lvl * 1048576 + (size_t)(b * 1024 + r * 32 + c) * IC;
    float acc[4] = {0.f, 0.f, 0.f, 0.f};
#pragma unroll
    for (int q = 0; q < 2; q++) {
        float4 a4 = *(const float4*)(af + lane * 8 + q * 4);
#pragma unroll
        for (int j = 0; j < 4; j++) {
            float4 w4 = *(const float4*)(hw + j * IC + lane * 8 + q * 4);
            acc[j] += a4.x * w4.x + a4.y * w4.y + a4.z * w4.z + a4.w * w4.w;
        }
    }
#pragma unroll
    for (int o = 16; o; o >>= 1)
#pragma unroll
        for (int j = 0; j < 4; j++) acc[j] += __shfl_down_sync(0xffffffffu, acc[j], o);
    if (lane == 0) {
        float p0 = sigm(acc[0] + hb[0]), p1 = sigm(acc[1] + hb[1]);
        float p2 = sigm(acc[2] + hb[2]), p3 = sigm(acc[3] + hb[3]);
        *(float4*)(out + finOff + (size_t)(b * nk + k) * 4) =
            make_float4((float)r - 16.f * p0, (float)c - 16.f * p1, (float)r + 16.f * p2, (float)c + 16.f * p3);
    }
}

extern "C" void kernel_launch(void* const* d_in, const int* in_sizes, int n_in, void* d_out, int out_size) {
    const float* feat0 = (const float*)d_in[0];
    const float* feat1 = (const float*)d_in[1];
    const float* feat2 = (const float*)d_in[2];
    const int* coords = (const int*)d_in[3];
    const float* ehw = (const float*)d_in[22];
    const float* ehb = (const float*)d_in[23];
    const float* hw = (const float*)d_in[24];
    const float* hb = (const float*)d_in[25];
    float* out = (float*)d_out;
    PrepArgs P;
    for (int t = 0; t < 3; t++) {
        int base = 4 + 6 * t;
        P.w[t] = (const float*)d_in[base]; P.b[t] = (const float*)d_in[base + 1];
        P.g[t] = (const float*)d_in[base + 2]; P.bb[t] = (const float*)d_in[base + 3];
        P.m[t] = (const float*)d_in[base + 4]; P.v[t] = (const float*)d_in[base + 5];
    }
    int prepN = 9 * IC + 3 * IC * 9 * IC + 2 * 9 * 32768;
    prep_k<<<(prepN + 255) / 256, 256>>>(P);
    splitF_k<<<32768, 256>>>(feat0);
    dummy_k<<<1, 32>>>();
    mega_k<<<3064, 256>>>(feat0, feat1, feat2, ehw);
    em_k<<<(86016 + 255) / 256, 256>>>(ehb, out);
    sort_k<<<dim3(3, 4), 512>>>(coords, out, ehb, out);
    head_k<<<dim3(128, 4, 3), 128>>>(coords, hw, hb, out);
}

// round 14
// speedup vs baseline: 1.0227x; 1.0227x over previous
#include <cuda_runtime.h>
#include <cuda_bf16.h>
#include <math.h>
#define IC 256
typedef unsigned long long u64; typedef unsigned int u32;

__device__ __align__(256) float g_xs[22020096];
__device__ __align__(256) float g_px[3 * 1048576];
__device__ __align__(256) float g_part[2][86016];
__device__ __align__(256) float g_partx[8192];
__device__ __align__(256) float g_partx1[8192];
__device__ __align__(256) float g_xc[1966080];
__device__ __align__(256) float g_xc1[1966080];
__device__ __align__(256) float g_wT[3][IC * 9 * IC];
__device__ __align__(256) float g_scale[3][3][IC];
__device__ __align__(256) float g_bias[3][3][IC];
__device__ int g_sel[3][4][512];
__device__ int g_cnt[8];
__device__ int g_rc[640];                 // [0..511] lvl0 rows, [512..639] lvl1 row-pairs
__device__ __align__(256) u32 gF0b[2 * 8388608];   // R10 layout [split][(b*128+cp)<<14 + yx]
__device__ __align__(256) u32 gXsb[2 * 8388608];
__device__ __align__(256) u32 gF1b[2 * 2097152];   // lvl1 [split][(b*128+cp)<<12 + yx]
__device__ __align__(256) u32 gX1b[2 * 2097152];
__device__ __align__(256) u32 gWb[2 * 2 * 9 * 16 * 2048];  // R10 layout

// FFMA2 stream (fi space, 688): shareC0,shareC1,share2, entC0,entC1,ent2, pat0,pat1,pat2
__constant__ int f_st[10] = {0, 120, 240, 304, 368, 432, 496, 560, 624, 688};
__constant__ int f_typ[9] = {3, 5, 0, 4, 6, 1, 2, 2, 2};
__constant__ int f_lvl[9] = {0, 1, 2, 0, 1, 2, 0, 1, 2};
__constant__ int f_tX[9]  = {3, 3, 2, 2, 2, 2, 2, 2, 2};
__constant__ int f_gi[9]  = {-1, -1, -1, 3, 4, 2, 0, 1, 2};
__constant__ int f_gn[9]  = {0, 0, 0, 120, 120, 64, 1024, 256, 64};

__device__ __forceinline__ u64 pack2(float v) {
    u64 d; unsigned r = __float_as_uint(v);
    asm("mov.b64 %0, {%1, %2};" : "=l"(d) : "r"(r), "r"(r)); return d;
}
__device__ __forceinline__ u64 ffma2(u64 a, u64 b, u64 c) {
    u64 d; asm("fma.rn.f32x2 %0, %1, %2, %3;" : "=l"(d) : "l"(a), "l"(b), "l"(c)); return d;
}
__device__ __forceinline__ void unpack2(u64 v, float& lo, float& hi) {
    unsigned a, b; asm("mov.b64 {%0, %1}, %2;" : "=r"(a), "=r"(b) : "l"(v));
    lo = __uint_as_float(a); hi = __uint_as_float(b);
}
__device__ __forceinline__ float sigm(float x) { return 1.f / (1.f + expf(-x)); }
__device__ __forceinline__ u32 bfpair(float lo, float hi) {
    __nv_bfloat162 h = __floats2bfloat162_rn(lo, hi);
    return *(u32*)&h;
}
__device__ __forceinline__ float bfres(float v) {
    return v - __bfloat162float(__float2bfloat16(v));
}
__device__ __forceinline__ void mmab(float* c, const u32* a, const u32* b) {
    asm volatile("mma.sync.aligned.m16n8k16.row.col.f32.bf16.bf16.f32 "
        "{%0,%1,%2,%3}, {%4,%5,%6,%7}, {%8,%9}, {%0,%1,%2,%3};"
        : "+f"(c[0]), "+f"(c[1]), "+f"(c[2]), "+f"(c[3])
        : "r"(a[0]), "r"(a[1]), "r"(a[2]), "r"(a[3]), "r"(b[0]), "r"(b[1]));
}

struct PrepArgs { const float *w[3], *b[3], *g[3], *bb[3], *m[3], *v[3]; };

__global__ void prep_k(PrepArgs P) {
    int idx = blockIdx.x * blockDim.x + threadIdx.x;
    if (idx < 8) g_cnt[idx] = 0;
    if (idx < 640) g_rc[idx] = 0;
    if (idx < 9 * IC) {
        int t = idx / (3 * IC), rem = idx % (3 * IC), l = rem / IC, ch = rem % IC;
        float s = P.g[t][l * IC + ch] / sqrtf(P.v[t][l * IC + ch] + 1e-5f);
        g_scale[t][l][ch] = s;
        g_bias[t][l][ch] = P.bb[t][l * IC + ch] + (P.b[t][ch] - P.m[t][l * IC + ch]) * s;
    }
    int j = idx - 9 * IC;
    if (j >= 0 && j < 3 * IC * 9 * IC) {
        int t = j / (IC * 9 * IC), rem = j % (IC * 9 * IC);
        int ci = rem / (9 * IC), tap = (rem / IC) % 9, n = rem % IC;
        g_wT[t][ci * 9 * IC + tap * IC + n] = P.w[t][n * IC * 9 + ci * 9 + tap];
    }
    int j2 = j - 3 * IC * 9 * IC;
    if (j2 >= 0 && j2 < 2 * 9 * 32768) {
        int t = j2 / (9 * 32768), rem = j2 % (9 * 32768);
        int tap = rem / 32768, r2 = rem % 32768;
        int c0p = r2 >> 11, cpl = (r2 >> 8) & 7, n = r2 & 255;
        int cp = c0p * 8 + cpl;
        float w0 = P.w[t][(n * 256 + 2 * cp) * 9 + tap];
        float w1 = P.w[t][(n * 256 + 2 * cp + 1) * 9 + tap];
        size_t o = ((size_t)((t * 2) * 9 + tap) * 16 + c0p) * 2048 + cpl * 256 + n;
        gWb[o] = bfpair(w0, w1);
        gWb[o + (size_t)9 * 32768] = bfpair(bfres(w0), bfres(w1));
    }
}

__global__ void splitF_k(const float* __restrict__ f0) {
    int i = blockIdx.x * blockDim.x + threadIdx.x;
    if (i >= 8388608) return;
    int b = i >> 21, rem = i & 2097151;
    int cp = rem >> 14, yx = rem & 16383;
    float v0 = f0[((size_t)(b * 256 + 2 * cp) * 16384) + yx];
    float v1 = f0[((size_t)(b * 256 + 2 * cp + 1) * 16384) + yx];
    size_t o = ((size_t)(b * 128 + cp) << 14) + yx;
    gF0b[o] = bfpair(v0, v1);
    gF0b[o + 8388608] = bfpair(bfres(v0), bfres(v1));
}

__global__ void splitF1_k(const float* __restrict__ f1) {
    int i = blockIdx.x * blockDim.x + threadIdx.x;
    if (i >= 2097152) return;
    int b = i >> 19, rem = i & 524287;
    int cp = rem >> 12, yx = rem & 4095;
    float v0 = f1[((size_t)(b * 256 + 2 * cp) * 4096) + yx];
    float v1 = f1[((size_t)(b * 256 + 2 * cp + 1) * 4096) + yx];
    size_t o = ((size_t)(b * 128 + cp) << 12) + yx;
    gF1b[o] = bfpair(v0, v1);
    gF1b[o + 2097152] = bfpair(bfres(v0), bfres(v1));
}

__global__ void dummy_k() {}

// exact FFMA2 conv body (verbatim)
__device__ __forceinline__ void ffmaConv(float* sBuf, int tid,
    const float* __restrict__ src, int srcH, int srcW, int y0, int x0,
    const float* __restrict__ wT, int nblk, const float* sc, const float* bi,
    int om, float* outX, int outW, int outPS, float* outPart, int partW,
    float* outPx, const float* __restrict__ ehw)
{
    float* sIn = sBuf; float* sW = sBuf + 1520;
    const int cg = tid >> 4, sg = tid & 15;
    const int srow = sg >> 1, sx = (sg & 1) * 8;
    u64 acc[4][8];
#pragma unroll
    for (int ii = 0; ii < 4; ii++)
#pragma unroll
        for (int j = 0; j < 8; j++) acc[ii][j] = 0ull;
    for (int c0 = 0; c0 < IC; c0 += 8) {
        for (int e = tid; e < 1520; e += 256) {
            int ci = e / 190, rem = e % 190, r = rem / 19, cc = rem % 19;
            int gy = y0 - 1 + r, gx = x0 - 1 + cc;
            float v = 0.f;
            if (cc < 18 && gy >= 0 && gy < srcH && gx >= 0 && gx < srcW)
                v = src[((size_t)(c0 + ci) * srcH + gy) * srcW + gx];
            sIn[e] = v;
        }
        for (int e4 = tid; e4 < 2304; e4 += 256) {
            int ci = e4 / 288, rem = e4 % 288, tap = rem / 32, n4 = rem % 32;
            float4 v = *(const float4*)(wT + (size_t)(c0 + ci) * (9 * IC) + tap * IC + nblk * 128 + n4 * 4);
            *(float4*)(sW + ci * 1152 + tap * 128 + n4 * 4) = v;
        }
        __syncthreads();
#pragma unroll 1
        for (int ci = 0; ci < 8; ci++) {
#pragma unroll
            for (int dy = 0; dy < 3; dy++) {
                const float* rp = sIn + ci * 190 + (srow + dy) * 19 + sx;
                u64 rr[10];
#pragma unroll
                for (int j = 0; j < 10; j++) rr[j] = pack2(rp[j]);
                const u64* wp = (const u64*)(sW + ci * 1152 + dy * 384 + cg * 8);
#pragma unroll
                for (int dx = 0; dx < 3; dx++) {
                    u64 w0 = wp[dx * 64], w1 = wp[dx * 64 + 1], w2 = wp[dx * 64 + 2], w3 = wp[dx * 64 + 3];
#pragma unroll
                    for (int m = 0; m < 8; m++) {
                        acc[0][m] = ffma2(w0, rr[m + dx], acc[0][m]);
                        acc[1][m] = ffma2(w1, rr[m + dx], acc[1][m]);
                        acc[2][m] = ffma2(w2, rr[m + dx], acc[2][m]);
                        acc[3][m] = ffma2(w3, rr[m + dx], acc[3][m]);
                    }
                }
            }
        }
        __syncthreads();
    }
    float psum[8];
#pragma unroll
    for (int m = 0; m < 8; m++) psum[m] = 0.f;
    const int y = y0 + srow, xb = x0 + sx;
#pragma unroll
    for (int n2 = 0; n2 < 4; n2++) {
        int cha = nblk * 128 + cg * 8 + 2 * n2, chb = cha + 1;
        float sa = sc[cha], ta = bi[cha], sb = sc[chb], tb = bi[chb];
        float va[8], vb[8];
#pragma unroll
        for (int m = 0; m < 8; m++) {
            float lo, hi; unpack2(acc[n2][m], lo, hi);
            va[m] = fmaxf(fmaf(lo, sa, ta), 0.f);
            vb[m] = fmaxf(fmaf(hi, sb, tb), 0.f);
        }
        if (om == 0) {
            float* oa = outX + (size_t)cha * outPS + y * outW + xb;
            float* ob = outX + (size_t)chb * outPS + y * outW + xb;
            *(float4*)(oa) = make_float4(va[0], va[1], va[2], va[3]);
            *(float4*)(oa + 4) = make_float4(va[4], va[5], va[6], va[7]);
            *(float4*)(ob) = make_float4(vb[0], vb[1], vb[2], vb[3]);
            *(float4*)(ob + 4) = make_float4(vb[4], vb[5], vb[6], vb[7]);
        } else if (om == 1) {
            float wa = ehw[cha], wb = ehw[chb];
#pragma unroll
            for (int m = 0; m < 8; m++) psum[m] += va[m] * wa + vb[m] * wb;
        } else {
#pragma unroll
            for (int m = 0; m < 8; m++) {
                float* o = outPx + (size_t)(y * 32 + xb + m) * IC;
                o[cha] = va[m]; o[chb] = vb[m];
            }
        }
    }
    if (om == 1) {
#pragma unroll
        for (int m = 0; m < 8; m++) sW[cg * 128 + srow * 16 + sx + m] = psum[m];
        __syncthreads();
        if (tid < 128) {
            float a2 = 0.f;
#pragma unroll
            for (int c2 = 0; c2 < 16; c2++) a2 += sW[c2 * 128 + tid];
            outPart[(y0 + (tid >> 4)) * partW + x0 + (tid & 15)] = a2;
        }
    }
}

__global__ __launch_bounds__(256, 2)
void mega_k(const float* __restrict__ f0, const float* __restrict__ f1,
            const float* __restrict__ f2, const float* __restrict__ ehw) {
    __shared__ __align__(16) float sBuf[10752];
    const int tid = threadIdx.x, wid = tid >> 5, lane = tid & 31;
    const int bid = blockIdx.x;

    int ti = -1, fi = -1;
    if (bid < 1024) ti = bid;
    else if (bid < 1264) fi = bid - 1024;
    else if (bid < 1520) ti = 2048 + (bid - 1264);
    else if (bid < 1584) fi = 240 + (bid - 1520);
    else if (bid < 2608) ti = 1024 + (bid - 1584);
    else if (bid < 2864) ti = 2304 + (bid - 2608);
    else fi = 304 + (bid - 2864);

    if (ti >= 0) {
        // ===== bf16 2-split tensor conv: lv=0 lvl0 (1 row), lv=1 lvl1 (row pair) =====
        const int lv = (ti >= 2048);
        const int tw = lv ? (ti >= 2304) : (ti >= 1024);
        const int i = lv ? (ti & 255) : (ti & 1023);
        const int yb = i >> 3, b = (i >> 1) & 3, nblk = i & 1;
        const int W = lv ? 64 : 128, Wm1 = W - 1, HH = W;
        const int ymax = lv ? 31 : 127;
        const int wx = wid & 3, wy = wid >> 2;
        u32* S = (u32*)sBuf;
        if (tw == 1) {
            if (tid == 0) {
                int lo = yb > 0 ? yb - 1 : 0, hi = yb < ymax ? yb + 1 : ymax;
                int rb = lv ? 512 + b * 32 : b * 128; long long gd = 0;
                for (int rr = lo; rr <= hi; rr++)
                    while (atomicAdd(&g_rc[rb + rr], 0) < 2 && gd < 400000000LL) gd++;
            }
            __syncthreads(); __threadfence();
        }
        const u32* __restrict__ plane = lv ? (tw ? gX1b : gF1b) : (tw ? gXsb : gF0b);
        const size_t psz = lv ? 2097152 : 8388608;
        float acc[16][4];
#pragma unroll
        for (int q = 0; q < 16; q++) { acc[q][0] = acc[q][1] = acc[q][2] = acc[q][3] = 0.f; }
        if (tid < 128) {
            int s = tid >> 6, cpl = (tid >> 3) & 7, k = tid & 7;
            S[s * 1088 + cpl * 136 + 128 + k] = 0;
        }

        for (int dy = 0; dy < 3; dy++) {
            for (int c0p = 0; c0p < 16; c0p++) {
                __syncthreads();
                for (int e = tid; e < 512; e += 256) {
                    int s = e >= 256, r = e - s * 256;
                    int cpl = r >> 5, x4 = (r & 31) * 4;
                    int iy, x;
                    if (lv) { iy = yb * 2 + dy - 1 + (x4 >= 64); x = x4 & 63; }
                    else { iy = yb + dy - 1; x = x4; }
                    uint4 v = make_uint4(0, 0, 0, 0);
                    if (iy >= 0 && iy < HH)
                        v = *(const uint4*)(plane + (size_t)s * psz +
                            ((size_t)(b * 128 + c0p * 8 + cpl) * HH + iy) * W + x);
                    *(uint4*)(S + s * 1088 + cpl * 136 + x4) = v;
                }
                for (int e = tid; e < 1536; e += 256) {
                    int s = e >= 768, r = e - s * 768;
                    int dx = r >> 8, rr = r & 255, cpl = rr >> 5, n4 = (rr & 31) * 4;
                    const u32* src = gWb + ((((size_t)(tw * 2 + s) * 9 + dy * 3 + dx) * 16 + c0p) * 2048) + cpl * 256 + nblk * 128 + n4;
                    *(uint4*)(S + 2176 + (s * 3 + dx) * 1088 + cpl * 136 + n4) = *(const uint4*)src;
                }
                __syncthreads();
#pragma unroll
                for (int dx = 0; dx < 3; dx++) {
                    u32 a[2][2][4];
#pragma unroll
                    for (int mf = 0; mf < 2; mf++) {
                        int p0 = wx * 32 + mf * 16 + (lane >> 2), p1 = p0 + 8;
                        int x0m = p0 & Wm1, x1m = p1 & Wm1;
                        int gx0 = x0m + dx - 1, gx1 = x1m + dx - 1;
                        int i0 = (gx0 >= 0 && gx0 < W) ? p0 - x0m + gx0 : 128;
                        int i1 = (gx1 >= 0 && gx1 < W) ? p1 - x1m + gx1 : 128;
#pragma unroll
                        for (int s = 0; s < 2; s++) {
                            int base = s * 1088 + (lane & 3) * 136;
                            a[s][mf][0] = S[base + i0]; a[s][mf][1] = S[base + i1];
                            a[s][mf][2] = S[base + 544 + i0]; a[s][mf][3] = S[base + 544 + i1];
                        }
                    }
#pragma unroll
                    for (int nt = 0; nt < 8; nt++) {
                        int bb = 2176 + dx * 1088 + (lane & 3) * 136 + wy * 64 + nt * 8 + (lane >> 2);
                        u32 b0[2] = {S[bb], S[bb + 544]};
                        u32 b1[2] = {S[bb + 3264], S[bb + 3264 + 544]};
#pragma unroll
                        for (int mf = 0; mf < 2; mf++) {
                            mmab(acc[mf * 8 + nt], a[0][mf], b0);
                            mmab(acc[mf * 8 + nt], a[0][mf], b1);
                            mmab(acc[mf * 8 + nt], a[1][mf], b0);
                        }
                    }
                }
            }
        }
        const float* sc = g_scale[tw][lv]; const float* bi = g_bias[tw][lv];
        float psum[4] = {0.f, 0.f, 0.f, 0.f};
#pragma unroll
        for (int mf = 0; mf < 2; mf++)
#pragma unroll
            for (int nt = 0; nt < 8; nt++)
#pragma unroll
                for (int h = 0; h < 2; h++) {
                    int px = wx * 32 + mf * 16 + (lane >> 2) + h * 8;
                    int ch0 = nblk * 128 + wy * 64 + nt * 8 + (lane & 3) * 2;
                    float v0 = fmaxf(fmaf(acc[mf * 8 + nt][h * 2], sc[ch0], bi[ch0]), 0.f);
                    float v1 = fmaxf(fmaf(acc[mf * 8 + nt][h * 2 + 1], sc[ch0 + 1], bi[ch0 + 1]), 0.f);
                    if (tw == 0) {
                        if (lv == 0) {
                            size_t o = ((size_t)(b * 256 + ch0) * 128 + yb) * 128 + px;
                            g_xs[o] = v0; g_xs[o + 16384] = v1;
                            size_t ob = (((size_t)b * 128 + (ch0 >> 1)) << 14) + yb * 128 + px;
                            gXsb[ob] = bfpair(v0, v1);
                            gXsb[ob + 8388608] = bfpair(bfres(v0), bfres(v1));
                        } else {
                            int yy = yb * 2 + (px >> 6), xx = px & 63;
                            size_t o = 16777216 + ((size_t)(b * 256 + ch0) * 64 + yy) * 64 + xx;
                            g_xs[o] = v0; g_xs[o + 4096] = v1;
                            size_t ob = (((size_t)b * 128 + (ch0 >> 1)) << 12) + yy * 64 + xx;
                            gX1b[ob] = bfpair(v0, v1);
                            gX1b[ob + 2097152] = bfpair(bfres(v0), bfres(v1));
                        }
                    } else psum[mf * 2 + h] += v0 * ehw[ch0] + v1 * ehw[ch0 + 1];
                }
        if (tw == 1) {
#pragma unroll
            for (int q = 0; q < 4; q++) {
                psum[q] += __shfl_xor_sync(0xffffffffu, psum[q], 1);
                psum[q] += __shfl_xor_sync(0xffffffffu, psum[q], 2);
            }
            __syncthreads();
            if ((lane & 3) == 0)
#pragma unroll
                for (int q = 0; q < 4; q++)
                    sBuf[wy * 128 + wx * 32 + (q & 1) * 8 + (q >> 1) * 16 + (lane >> 2)] = psum[q];
            __syncthreads();
            if (tid < 128) {
                int p = tid;
                int po = lv ? 65536 + b * 4096 + (yb * 2 + (p >> 6)) * 64 + (p & 63)
                            : b * 16384 + yb * 128 + p;
                g_part[nblk][po] = sBuf[p] + sBuf[128 + p];
            }
        } else {
            __threadfence(); __syncthreads();
            if (tid == 0) {
                atomicAdd(&g_rc[(lv ? 512 + b * 32 : b * 128) + yb], 1);
                atomicAdd(&g_cnt[lv], 1);
            }
        }
        return;
    }

    // ===== FFMA2 segments =====
    int s = 0; while (s < 9 && !(fi >= f_st[s] && fi < f_st[s + 1])) s++;
    const int typ = f_typ[s], lvl = f_lvl[s], tX = f_tX[s];
    const int i = fi - f_st[s];
    const int tile = i >> 3, b = (i >> 1) & 3, nblk = i & 1;
    const int y0 = (tile / tX) * 8, x0 = (tile % tX) * 16;
    if (f_gi[s] >= 0) {
        if (tid == 0) {
            long long gd = 0;
            while (atomicAdd(&g_cnt[f_gi[s]], 0) < f_gn[s] && gd < 400000000LL) gd++;
        }
        __syncthreads(); __threadfence();
    }
    int tower = (typ == 0 || typ == 3 || typ == 5) ? 0 : ((typ == 1 || typ == 4 || typ == 6) ? 1 : 2);
    const float* sc = g_scale[tower][lvl];
    const float* bi = g_bias[tower][lvl];
    const float* wT = g_wT[tower];

    if (typ == 3) {          // shareC0: feat0 corner -> g_xc
        ffmaConv(sBuf, tid, f0 + (size_t)b * IC * 16384, 128, 128, y0, x0, wT, nblk, sc, bi,
                 0, g_xc + (size_t)b * IC * 1920, 48, 1920, nullptr, 0, nullptr, ehw);
        __threadfence(); __syncthreads();
        if (tid == 0) atomicAdd(&g_cnt[3], 1);
    } else if (typ == 5) {   // shareC1: feat1 corner -> g_xc1
        ffmaConv(sBuf, tid, f1 + (size_t)b * IC * 4096, 64, 64, y0, x0, wT, nblk, sc, bi,
                 0, g_xc1 + (size_t)b * IC * 1920, 48, 1920, nullptr, 0, nullptr, ehw);
        __threadfence(); __syncthreads();
        if (tid == 0) atomicAdd(&g_cnt[4], 1);
    } else if (typ == 0) {   // share2
        ffmaConv(sBuf, tid, f2 + (size_t)b * IC * 1024, 32, 32, y0, x0, wT, nblk, sc, bi,
                 0, g_xs + 20971520 + (size_t)b * IC * 1024, 32, 1024, nullptr, 0, nullptr, ehw);
        __threadfence(); __syncthreads();
        if (tid == 0) atomicAdd(&g_cnt[2], 1);
    } else if (typ == 4) {   // entC0 exact
        ffmaConv(sBuf, tid, g_xc + (size_t)b * IC * 1920, 40, 48, y0, x0, wT, nblk, sc, bi,
                 1, nullptr, 0, 0, g_partx + nblk * 4096 + b * 1024, 32, nullptr, ehw);
    } else if (typ == 6) {   // entC1 exact
        ffmaConv(sBuf, tid, g_xc1 + (size_t)b * IC * 1920, 40, 48, y0, x0, wT, nblk, sc, bi,
                 1, nullptr, 0, 0, g_partx1 + nblk * 4096 + b * 1024, 32, nullptr, ehw);
    } else if (typ == 1) {   // ent2
        ffmaConv(sBuf, tid, g_xs + 20971520 + (size_t)b * IC * 1024, 32, 32, y0, x0, wT, nblk, sc, bi,
                 1, nullptr, 0, 0, g_part[nblk] + 81920 + b * 1024, 32, nullptr, ehw);
    } else {                 // pat lvl 0/1/2
        int Hs = (lvl == 0) ? 128 : ((lvl == 1) ? 64 : 32);
        size_t xsoff = (lvl == 0) ? 0ul : ((lvl == 1) ? 16777216ul : 20971520ul);
        ffmaConv(sBuf, tid, g_xs + xsoff + (size_t)b * IC * Hs * Hs, Hs, Hs, y0, x0, wT, nblk, sc, bi,
                 2, nullptr, 0, 0, nullptr, 0, g_px + (size_t)lvl * 1048576 + (size_t)b * 1024 * IC, ehw);
    }
}

__global__ void em_k(const float* __restrict__ ehb, float* __restrict__ out) {
    int i = blockIdx.x * blockDim.x + threadIdx.x;
    if (i >= 86016) return;
    int emo = (i < 65536) ? 0 : ((i < 81920) ? 77824 - 65536 : 100352 - 81920);
    out[emo + i] = sigm(g_part[0][i] + g_part[1][i] + ehb[0]);
}

__global__ void sort_k(const int* __restrict__ coords, const float* __restrict__ base,
                       const float* __restrict__ ehb, float* __restrict__ out) {
    __shared__ u64 sk[1024];
    int lvl = blockIdx.x, b = blockIdx.y, t = threadIdx.x;
    int H = (lvl == 0) ? 128 : ((lvl == 1) ? 64 : 32);
    int nk = (lvl == 0) ? 512 : ((lvl == 1) ? 256 : 128);
    int emOff = (lvl == 0) ? 0 : ((lvl == 1) ? 77824 : 100352);
    int xyOff = (lvl == 0) ? 73728 : ((lvl == 1) ? 98304 : 106496);
    const float* em = base + emOff + b * H * H;
    for (int p = t; p < 1024; p += 512) {
        int r = coords[p], c = coords[1024 + p];
        float v;
        if (lvl == 0) v = sigm(g_partx[b * 1024 + r * 32 + c] + g_partx[4096 + b * 1024 + r * 32 + c] + ehb[0]);
        else if (lvl == 1) v = sigm(g_partx1[b * 1024 + r * 32 + c] + g_partx1[4096 + b * 1024 + r * 32 + c] + ehb[0]);
        else v = em[r * H + c];
        u64 key = ((u64)__float_as_uint(v) << 32) | (u32)(1023 - p);
        sk[p] = ~key;
    }
    __syncthreads();
    for (int k = 2; k <= 1024; k <<= 1)
        for (int j = k >> 1; j > 0; j >>= 1) {
            for (int i2 = t; i2 < 1024; i2 += 512) {
                int l = i2 ^ j;
                if (l > i2) {
                    u64 a = sk[i2], bb = sk[l];
                    if ((a > bb) == ((i2 & k) == 0)) { sk[i2] = bb; sk[l] = a; }
                }
            }
            __syncthreads();
        }
    if (t < nk) {
        int p = 1023 - (int)((~sk[t]) & 0xFFFFFFFFu);
        g_sel[lvl][b][t] = p;
        out[xyOff + (b * nk + t) * 2] = (float)coords[p];
        out[xyOff + (b * nk + t) * 2 + 1] = (float)coords[1024 + p];
    }
}

__global__ void head_k(const int* __restrict__ coords, const float* __restrict__ hw,
                       const float* __restrict__ hb, float* __restrict__ out) {
    int lvl = blockIdx.z, b = blockIdx.y;
    int nk = (lvl == 0) ? 512 : ((lvl == 1) ? 256 : 128);
    int finOff = (lvl == 0) ? 65536 : ((lvl == 1) ? 94208 : 104448);
    int k = blockIdx.x * 4 + (threadIdx.x >> 5), lane = threadIdx.x & 31;
    if (k >= nk) return;
    int p = g_sel[lvl][b][k];
    int r = coords[p], c = coords[1024 + p];
    const float* af = g_px + (size_t)lvl * 1048576 + (size_t)(b * 1024 + r * 32 + c) * IC;
    float acc[4] = {0.f, 0.f, 0.f, 0.f};
#pragma unroll
    for (int q = 0; q < 2; q++) {
        float4 a4 = *(const float4*)(af + lane * 8 + q * 4);
#pragma unroll
        for (int j = 0; j < 4; j++) {
            float4 w4 = *(const float4*)(hw + j * IC + lane * 8 + q * 4);
            acc[j] += a4.x * w4.x + a4.y * w4.y + a4.z * w4.z + a4.w * w4.w;
        }
    }
#pragma unroll
    for (int o = 16; o; o >>= 1)
#pragma unroll
        for (int j = 0; j < 4; j++) acc[j] += __shfl_down_sync(0xffffffffu, acc[j], o);
    if (lane == 0) {
        float p0 = sigm(acc[0] + hb[0]), p1 = sigm(acc[1] + hb[1]);
        float p2 = sigm(acc[2] + hb[2]), p3 = sigm(acc[3] + hb[3]);
        *(float4*)(out + finOff + (size_t)(b * nk + k) * 4) =
            make_float4((float)r - 16.f * p0, (float)c - 16.f * p1, (float)r + 16.f * p2, (float)c + 16.f * p3);
    }
}

extern "C" void kernel_launch(void* const* d_in, const int* in_sizes, int n_in, void* d_out, int out_size) {
    const float* feat0 = (const float*)d_in[0];
    const float* feat1 = (const float*)d_in[1];
    const float* feat2 = (const float*)d_in[2];
    const int* coords = (const int*)d_in[3];
    const float* ehw = (const float*)d_in[22];
    const float* ehb = (const float*)d_in[23];
    const float* hw = (const float*)d_in[24];
    const float* hb = (const float*)d_in[25];
    float* out = (float*)d_out;
    PrepArgs P;
    for (int t = 0; t < 3; t++) {
        int base = 4 + 6 * t;
        P.w[t] = (const float*)d_in[base]; P.b[t] = (const float*)d_in[base + 1];
        P.g[t] = (const float*)d_in[base + 2]; P.bb[t] = (const float*)d_in[base + 3];
        P.m[t] = (const float*)d_in[base + 4]; P.v[t] = (const float*)d_in[base + 5];
    }
    int prepN = 9 * IC + 3 * IC * 9 * IC + 2 * 9 * 32768;
    prep_k<<<(prepN + 255) / 256, 256>>>(P);
    splitF_k<<<32768, 256>>>(feat0);
    splitF1_k<<<8192, 256>>>(feat1);
    dummy_k<<<1, 32>>>();
    mega_k<<<3248, 256>>>(feat0, feat1, feat2, ehw);
    em_k<<<(86016 + 255) / 256, 256>>>(ehb, out);
    sort_k<<<dim3(3, 4), 512>>>(coords, out, ehb, out);
    head_k<<<dim3(128, 4, 3), 128>>>(coords, hw, hb, out);
}

// round 15
// speedup vs baseline: 1.0659x; 1.0422x over previous
#include <cuda_runtime.h>
#include <cuda_bf16.h>
#include <math.h>
#define IC 256
typedef unsigned long long u64; typedef unsigned int u32;

__device__ __align__(256) float g_xs[22020096];
__device__ __align__(256) float g_px[3 * 1048576];
__device__ __align__(256) float g_part[2][86016];
__device__ __align__(256) float g_partx[8192];
__device__ __align__(256) float g_xc[1966080];
__device__ __align__(256) float g_wT[3][IC * 9 * IC];
__device__ __align__(256) float g_scale[3][3][IC];
__device__ __align__(256) float g_bias[3][3][IC];
__device__ int g_sel[3][4][512];
__device__ int g_cnt[4];
__device__ int g_rc[512];
// bf16 split planes (R10 layout): [split][(b*128+cp)<<14 + yx]
__device__ __align__(256) u32 gF0b[2 * 8388608];
__device__ __align__(256) u32 gXsb[2 * 8388608];
// bf16 split weights, B k-half interleaved: [(t*2+s)*9+tap][c0p][cpl4][n][half]
__device__ __align__(256) u32 gWb[2 * 2 * 9 * 16 * 2048];

__constant__ int f_st[10] = {1024, 1144, 1400, 2488, 2552, 2808, 2872, 2936, 3000, 3064};
__constant__ int f_typ[9] = {3, 0, 0, 4, 1, 2, 1, 2, 2};
__constant__ int f_lvl[9] = {0, 1, 2, 0, 1, 1, 2, 2, 0};
__constant__ int f_tX[9]  = {3, 4, 2, 2, 4, 2, 2, 2, 2};
__constant__ int f_gi[9]  = {-1, -1, -1, 3, 1, 1, 2, 2, 0};
__constant__ int f_gn[9]  = {0, 0, 0, 120, 256, 256, 64, 64, 1024};

__device__ __forceinline__ u64 pack2(float v) {
    u64 d; unsigned r = __float_as_uint(v);
    asm("mov.b64 %0, {%1, %2};" : "=l"(d) : "r"(r), "r"(r)); return d;
}
__device__ __forceinline__ u64 ffma2(u64 a, u64 b, u64 c) {
    u64 d; asm("fma.rn.f32x2 %0, %1, %2, %3;" : "=l"(d) : "l"(a), "l"(b), "l"(c)); return d;
}
__device__ __forceinline__ void unpack2(u64 v, float& lo, float& hi) {
    unsigned a, b; asm("mov.b64 {%0, %1}, %2;" : "=r"(a), "=r"(b) : "l"(v));
    lo = __uint_as_float(a); hi = __uint_as_float(b);
}
__device__ __forceinline__ float sigm(float x) { return 1.f / (1.f + expf(-x)); }
__device__ __forceinline__ u32 bfpair(float lo, float hi) {
    __nv_bfloat162 h = __floats2bfloat162_rn(lo, hi);
    return *(u32*)&h;
}
__device__ __forceinline__ float bfres(float v) {
    return v - __bfloat162float(__float2bfloat16(v));
}
__device__ __forceinline__ void mmab(float* c, const u32* a, const u32* b) {
    asm volatile("mma.sync.aligned.m16n8k16.row.col.f32.bf16.bf16.f32 "
        "{%0,%1,%2,%3}, {%4,%5,%6,%7}, {%8,%9}, {%0,%1,%2,%3};"
        : "+f"(c[0]), "+f"(c[1]), "+f"(c[2]), "+f"(c[3])
        : "r"(a[0]), "r"(a[1]), "r"(a[2]), "r"(a[3]), "r"(b[0]), "r"(b[1]));
}

struct PrepArgs { const float *w[3], *b[3], *g[3], *bb[3], *m[3], *v[3]; };

__global__ void prep_k(PrepArgs P) {
    int idx = blockIdx.x * blockDim.x + threadIdx.x;
    if (idx < 4) g_cnt[idx] = 0;
    if (idx < 512) g_rc[idx] = 0;
    if (idx < 9 * IC) {
        int t = idx / (3 * IC), rem = idx % (3 * IC), l = rem / IC, ch = rem % IC;
        float s = P.g[t][l * IC + ch] / sqrtf(P.v[t][l * IC + ch] + 1e-5f);
        g_scale[t][l][ch] = s;
        g_bias[t][l][ch] = P.bb[t][l * IC + ch] + (P.b[t][ch] - P.m[t][l * IC + ch]) * s;
    }
    int j = idx - 9 * IC;
    if (j >= 0 && j < 3 * IC * 9 * IC) {
        int t = j / (IC * 9 * IC), rem = j % (IC * 9 * IC);
        int ci = rem / (9 * IC), tap = (rem / IC) % 9, n = rem % IC;
        g_wT[t][ci * 9 * IC + tap * IC + n] = P.w[t][n * IC * 9 + ci * 9 + tap];
    }
    int j2 = j - 3 * IC * 9 * IC;
    if (j2 >= 0 && j2 < 2 * 9 * 32768) {
        int t = j2 / (9 * 32768), rem = j2 % (9 * 32768);
        int tap = rem / 32768, r2 = rem % 32768;
        int c0p = r2 >> 11, cpl = (r2 >> 8) & 7, n = r2 & 255;
        int cp = c0p * 8 + cpl;
        float w0 = P.w[t][(n * 256 + 2 * cp) * 9 + tap];
        float w1 = P.w[t][(n * 256 + 2 * cp + 1) * 9 + tap];
        size_t o = ((size_t)((t * 2) * 9 + tap) * 16 + c0p) * 2048 + (cpl & 3) * 512 + n * 2 + (cpl >> 2);
        gWb[o] = bfpair(w0, w1);
        gWb[o + (size_t)9 * 32768] = bfpair(bfres(w0), bfres(w1));
    }
}

__global__ void splitF_k(const float* __restrict__ f0) {
    int i = blockIdx.x * blockDim.x + threadIdx.x;
    if (i >= 8388608) return;
    int b = i >> 21, rem = i & 2097151;
    int cp = rem >> 14, yx = rem & 16383;
    float v0 = f0[((size_t)(b * 256 + 2 * cp) * 16384) + yx];
    float v1 = f0[((size_t)(b * 256 + 2 * cp + 1) * 16384) + yx];
    size_t o = ((size_t)(b * 128 + cp) << 14) + yx;
    gF0b[o] = bfpair(v0, v1);
    gF0b[o + 8388608] = bfpair(bfres(v0), bfres(v1));
}

__global__ void dummy_k() {}

// exact FFMA2 conv body (verbatim)
__device__ __forceinline__ void ffmaConv(float* sBuf, int tid,
    const float* __restrict__ src, int srcH, int srcW, int y0, int x0,
    const float* __restrict__ wT, int nblk, const float* sc, const float* bi,
    int om, float* outX, int outW, int outPS, float* outPart, int partW,
    float* outPx, const float* __restrict__ ehw)
{
    float* sIn = sBuf; float* sW = sBuf + 1520;
    const int cg = tid >> 4, sg = tid & 15;
    const int srow = sg >> 1, sx = (sg & 1) * 8;
    u64 acc[4][8];
#pragma unroll
    for (int ii = 0; ii < 4; ii++)
#pragma unroll
        for (int j = 0; j < 8; j++) acc[ii][j] = 0ull;
    for (int c0 = 0; c0 < IC; c0 += 8) {
        for (int e = tid; e < 1520; e += 256) {
            int ci = e / 190, rem = e % 190, r = rem / 19, cc = rem % 19;
            int gy = y0 - 1 + r, gx = x0 - 1 + cc;
            float v = 0.f;
            if (cc < 18 && gy >= 0 && gy < srcH && gx >= 0 && gx < srcW)
                v = src[((size_t)(c0 + ci) * srcH + gy) * srcW + gx];
            sIn[e] = v;
        }
        for (int e4 = tid; e4 < 2304; e4 += 256) {
            int ci = e4 / 288, rem = e4 % 288, tap = rem / 32, n4 = rem % 32;
            float4 v = *(const float4*)(wT + (size_t)(c0 + ci) * (9 * IC) + tap * IC + nblk * 128 + n4 * 4);
            *(float4*)(sW + ci * 1152 + tap * 128 + n4 * 4) = v;
        }
        __syncthreads();
#pragma unroll 1
        for (int ci = 0; ci < 8; ci++) {
#pragma unroll
            for (int dy = 0; dy < 3; dy++) {
                const float* rp = sIn + ci * 190 + (srow + dy) * 19 + sx;
                u64 rr[10];
#pragma unroll
                for (int j = 0; j < 10; j++) rr[j] = pack2(rp[j]);
                const u64* wp = (const u64*)(sW + ci * 1152 + dy * 384 + cg * 8);
#pragma unroll
                for (int dx = 0; dx < 3; dx++) {
                    u64 w0 = wp[dx * 64], w1 = wp[dx * 64 + 1], w2 = wp[dx * 64 + 2], w3 = wp[dx * 64 + 3];
#pragma unroll
                    for (int m = 0; m < 8; m++) {
                        acc[0][m] = ffma2(w0, rr[m + dx], acc[0][m]);
                        acc[1][m] = ffma2(w1, rr[m + dx], acc[1][m]);
                        acc[2][m] = ffma2(w2, rr[m + dx], acc[2][m]);
                        acc[3][m] = ffma2(w3, rr[m + dx], acc[3][m]);
                    }
                }
            }
        }
        __syncthreads();
    }
    float psum[8];
#pragma unroll
    for (int m = 0; m < 8; m++) psum[m] = 0.f;
    const int y = y0 + srow, xb = x0 + sx;
#pragma unroll
    for (int n2 = 0; n2 < 4; n2++) {
        int cha = nblk * 128 + cg * 8 + 2 * n2, chb = cha + 1;
        float sa = sc[cha], ta = bi[cha], sb = sc[chb], tb = bi[chb];
        float va[8], vb[8];
#pragma unroll
        for (int m = 0; m < 8; m++) {
            float lo, hi; unpack2(acc[n2][m], lo, hi);
            va[m] = fmaxf(fmaf(lo, sa, ta), 0.f);
            vb[m] = fmaxf(fmaf(hi, sb, tb), 0.f);
        }
        if (om == 0) {
            float* oa = outX + (size_t)cha * outPS + y * outW + xb;
            float* ob = outX + (size_t)chb * outPS + y * outW + xb;
            *(float4*)(oa) = make_float4(va[0], va[1], va[2], va[3]);
            *(float4*)(oa + 4) = make_float4(va[4], va[5], va[6], va[7]);
            *(float4*)(ob) = make_float4(vb[0], vb[1], vb[2], vb[3]);
            *(float4*)(ob + 4) = make_float4(vb[4], vb[5], vb[6], vb[7]);
        } else if (om == 1) {
            float wa = ehw[cha], wb = ehw[chb];
#pragma unroll
            for (int m = 0; m < 8; m++) psum[m] += va[m] * wa + vb[m] * wb;
        } else {
#pragma unroll
            for (int m = 0; m < 8; m++) {
                float* o = outPx + (size_t)(y * 32 + xb + m) * IC;
                o[cha] = va[m]; o[chb] = vb[m];
            }
        }
    }
    if (om == 1) {
#pragma unroll
        for (int m = 0; m < 8; m++) sW[cg * 128 + srow * 16 + sx + m] = psum[m];
        __syncthreads();
        if (tid < 128) {
            float a2 = 0.f;
#pragma unroll
            for (int c2 = 0; c2 < 16; c2++) a2 += sW[c2 * 128 + tid];
            outPart[(y0 + (tid >> 4)) * partW + x0 + (tid & 15)] = a2;
        }
    }
}

__global__ __launch_bounds__(256, 2)
void mega_k(const float* __restrict__ f0, const float* __restrict__ f1,
            const float* __restrict__ f2, const float* __restrict__ ehw) {
    __shared__ __align__(16) float sBuf[10752];
    const int tid = threadIdx.x, wid = tid >> 5, lane = tid & 31;
    const int bid = blockIdx.x;

    if (bid < 1024 || (bid >= 1464 && bid < 2488)) {
        // ===== bf16 2-split tensor conv lvl0: A scalar frags (R10), B LDS.64 pair frags =====
        const int tw = (bid >= 1464), i = tw ? bid - 1464 : bid;
        const int y = i >> 3, b = (i >> 1) & 3, nblk = i & 1;
        const int wx = wid & 3, wy = wid >> 2;
        u32* S = (u32*)sBuf;   // A: [2s][8cpl][136] @0 (2176) ; B @2176: [2s][3dx]{1088}: [4cpl4][128n][2half] stride 264
        if (tw == 1) {
            if (tid == 0) {
                int lo = y > 0 ? y - 1 : 0, hi = y < 127 ? y + 1 : 127; long long gd = 0;
                for (int rr = lo; rr <= hi; rr++)
                    while (atomicAdd(&g_rc[b * 128 + rr], 0) < 2 && gd < 400000000LL) gd++;
            }
            __syncthreads(); __threadfence();
        }
        const u32* __restrict__ plane = tw ? gXsb : gF0b;
        float acc[16][4];
#pragma unroll
        for (int q = 0; q < 16; q++) { acc[q][0] = acc[q][1] = acc[q][2] = acc[q][3] = 0.f; }
        if (tid < 128) {   // zero A halo px=128..135
            int s = tid >> 6, cpl = (tid >> 3) & 7, k = tid & 7;
            S[s * 1088 + cpl * 136 + 128 + k] = 0;
        }

        int dys[3]; int nd = 0;
#pragma unroll
        for (int dy = 0; dy < 3; dy++) { int iy = y + dy - 1; if (iy >= 0 && iy < 128) dys[nd++] = dy; }

        for (int di = 0; di < nd; di++) {
            int dy = dys[di], iy = y + dy - 1;
            for (int c0p = 0; c0p < 16; c0p++) {
                __syncthreads();
                for (int e = tid; e < 512; e += 256) {       // A stage uint4 (R10)
                    int s = e >= 256, r = e - s * 256;
                    int cpl = r >> 5, x4 = (r & 31) * 4;
                    uint4 v = *(const uint4*)(plane + (size_t)s * 8388608 +
                        (((size_t)(b * 128 + c0p * 8 + cpl)) << 14) + iy * 128 + x4);
                    *(uint4*)(S + s * 1088 + cpl * 136 + x4) = v;
                }
                for (int e = tid; e < 1536; e += 256) {      // B stage uint4 (pair layout)
                    int s = e >= 768, r = e - s * 768;
                    int dx = r >> 8, rr = r & 255, cpl4 = rr >> 6, ng = rr & 63;
                    const u32* src = gWb + ((size_t)((tw * 2 + s) * 9 + dy * 3 + dx) * 16 + c0p) * 2048
                                     + cpl4 * 512 + nblk * 256 + ng * 4;
                    *(uint4*)(S + 2176 + (s * 3 + dx) * 1088 + cpl4 * 264 + ng * 4) = *(const uint4*)src;
                }
                __syncthreads();
#pragma unroll
                for (int dx = 0; dx < 3; dx++) {
                    u32 a[2][2][4];
#pragma unroll
                    for (int mf = 0; mf < 2; mf++) {
                        int px = wx * 32 + mf * 16 + (lane >> 2);
                        int g0 = px + dx - 1, g1 = g0 + 8;
                        int i0 = (g0 >= 0 && g0 < 128) ? g0 : 128;
                        int i1 = (g1 < 128) ? g1 : 128;
#pragma unroll
                        for (int s = 0; s < 2; s++) {
                            int base = s * 1088 + (lane & 3) * 136;
                            a[s][mf][0] = S[base + i0]; a[s][mf][1] = S[base + i1];
                            a[s][mf][2] = S[base + 544 + i0]; a[s][mf][3] = S[base + 544 + i1];
                        }
                    }
#pragma unroll
                    for (int nt = 0; nt < 8; nt++) {
                        int bb = 2176 + dx * 1088 + (lane & 3) * 264 + (wy * 64 + nt * 8 + (lane >> 2)) * 2;
                        u32 b0[2], b1[2];
                        *(u64*)b0 = *(const u64*)(S + bb);
                        *(u64*)b1 = *(const u64*)(S + bb + 3264);
#pragma unroll
                        for (int mf = 0; mf < 2; mf++) {
                            mmab(acc[mf * 8 + nt], a[0][mf], b0);
                            mmab(acc[mf * 8 + nt], a[0][mf], b1);
                            mmab(acc[mf * 8 + nt], a[1][mf], b0);
                        }
                    }
                }
            }
        }
        const float* sc = g_scale[tw][0]; const float* bi = g_bias[tw][0];
        float psum[4] = {0.f, 0.f, 0.f, 0.f};
#pragma unroll
        for (int mf = 0; mf < 2; mf++)
#pragma unroll
            for (int nt = 0; nt < 8; nt++)
#pragma unroll
                for (int h = 0; h < 2; h++) {
                    int px = wx * 32 + mf * 16 + (lane >> 2) + h * 8;
                    int ch0 = nblk * 128 + wy * 64 + nt * 8 + (lane & 3) * 2;
                    float v0 = fmaxf(fmaf(acc[mf * 8 + nt][h * 2], sc[ch0], bi[ch0]), 0.f);
                    float v1 = fmaxf(fmaf(acc[mf * 8 + nt][h * 2 + 1], sc[ch0 + 1], bi[ch0 + 1]), 0.f);
                    if (tw == 0) {
                        size_t o = ((size_t)(b * 256 + ch0) * 128 + y) * 128 + px;
                        g_xs[o] = v0; g_xs[o + 16384] = v1;
                        size_t ob = (((size_t)b * 128 + (ch0 >> 1)) << 14) + y * 128 + px;
                        gXsb[ob] = bfpair(v0, v1);
                        gXsb[ob + 8388608] = bfpair(bfres(v0), bfres(v1));
                    } else psum[mf * 2 + h] += v0 * ehw[ch0] + v1 * ehw[ch0 + 1];
                }
        if (tw == 1) {
#pragma unroll
            for (int q = 0; q < 4; q++) {
                psum[q] += __shfl_xor_sync(0xffffffffu, psum[q], 1);
                psum[q] += __shfl_xor_sync(0xffffffffu, psum[q], 2);
            }
            __syncthreads();
            if ((lane & 3) == 0)
#pragma unroll
                for (int q = 0; q < 4; q++)
                    sBuf[wy * 128 + wx * 32 + (q & 1) * 8 + (q >> 1) * 16 + (lane >> 2)] = psum[q];
            __syncthreads();
            if (tid < 128) g_part[nblk][b * 16384 + y * 128 + tid] = sBuf[tid] + sBuf[128 + tid];
        } else {
            __threadfence(); __syncthreads();
            if (tid == 0) { atomicAdd(&g_rc[b * 128 + y], 1); atomicAdd(&g_cnt[0], 1); }
        }
        return;
    }

    // ===== FFMA2 segments (verbatim from passing R10/R12) =====
    int s = 0; while (s < 9 && !(bid >= f_st[s] && bid < f_st[s + 1])) s++;
    const int typ = f_typ[s], lvl = f_lvl[s], tX = f_tX[s];
    const int i = bid - f_st[s];
    const int tile = i >> 3, b = (i >> 1) & 3, nblk = i & 1;
    const int y0 = (tile / tX) * 8, x0 = (tile % tX) * 16;
    if (f_gi[s] >= 0) {
        if (tid == 0) {
            long long gd = 0;
            while (atomicAdd(&g_cnt[f_gi[s]], 0) < f_gn[s] && gd < 400000000LL) gd++;
        }
        __syncthreads(); __threadfence();
    }
    const int Hs = (lvl == 0) ? 128 : ((lvl == 1) ? 64 : 32);
    const size_t xsoff = (lvl == 0) ? 0ul : ((lvl == 1) ? 16777216ul : 20971520ul);
    int tower = (typ == 0 || typ == 3) ? 0 : ((typ == 1 || typ == 4) ? 1 : 2);
    const float* sc = g_scale[tower][lvl];
    const float* bi = g_bias[tower][lvl];
    const float* wT = g_wT[tower];

    if (typ == 3) {
        ffmaConv(sBuf, tid, f0 + (size_t)b * IC * 16384, 128, 128, y0, x0, wT, nblk, sc, bi,
                 0, g_xc + (size_t)b * IC * 1920, 48, 1920, nullptr, 0, nullptr, ehw);
        __threadfence(); __syncthreads();
        if (tid == 0) atomicAdd(&g_cnt[3], 1);
    } else if (typ == 0) {
        const float* src = ((lvl == 1) ? f1 : f2) + (size_t)b * IC * Hs * Hs;
        ffmaConv(sBuf, tid, src, Hs, Hs, y0, x0, wT, nblk, sc, bi,
                 0, g_xs + xsoff + (size_t)b * IC * Hs * Hs, Hs, Hs * Hs, nullptr, 0, nullptr, ehw);
        __threadfence(); __syncthreads();
        if (tid == 0) atomicAdd(&g_cnt[lvl], 1);
    } else if (typ == 4) {
        ffmaConv(sBuf, tid, g_xc + (size_t)b * IC * 1920, 40, 48, y0, x0, wT, nblk, sc, bi,
                 1, nullptr, 0, 0, g_partx + nblk * 4096 + b * 1024, 32, nullptr, ehw);
    } else if (typ == 1) {
        int po = (lvl == 1) ? 65536 : 81920;
        ffmaConv(sBuf, tid, g_xs + xsoff + (size_t)b * IC * Hs * Hs, Hs, Hs, y0, x0, wT, nblk, sc, bi,
                 1, nullptr, 0, 0, g_part[nblk] + po + b * Hs * Hs, Hs, nullptr, ehw);
    } else {
        ffmaConv(sBuf, tid, g_xs + xsoff + (size_t)b * IC * Hs * Hs, Hs, Hs, y0, x0, wT, nblk, sc, bi,
                 2, nullptr, 0, 0, nullptr, 0, g_px + (size_t)lvl * 1048576 + (size_t)b * 1024 * IC, ehw);
    }
}

__global__ void em_k(const float* __restrict__ ehb, float* __restrict__ out) {
    int i = blockIdx.x * blockDim.x + threadIdx.x;
    if (i >= 86016) return;
    int emo = (i < 65536) ? 0 : ((i < 81920) ? 77824 - 65536 : 100352 - 81920);
    out[emo + i] = sigm(g_part[0][i] + g_part[1][i] + ehb[0]);
}

__global__ void sort_k(const int* __restrict__ coords, const float* __restrict__ base,
                       const float* __restrict__ ehb, float* __restrict__ out) {
    __shared__ u64 sk[1024];
    int lvl = blockIdx.x, b = blockIdx.y, t = threadIdx.x;
    int H = (lvl == 0) ? 128 : ((lvl == 1) ? 64 : 32);
    int nk = (lvl == 0) ? 512 : ((lvl == 1) ? 256 : 128);
    int emOff = (lvl == 0) ? 0 : ((lvl == 1) ? 77824 : 100352);
    int xyOff = (lvl == 0) ? 73728 : ((lvl == 1) ? 98304 : 106496);
    const float* em = base + emOff + b * H * H;
    for (int p = t; p < 1024; p += 512) {
        int r = coords[p], c = coords[1024 + p];
        float v = (lvl == 0) ? sigm(g_partx[b * 1024 + r * 32 + c] + g_partx[4096 + b * 1024 + r * 32 + c] + ehb[0])
                             : em[r * H + c];
        u64 key = ((u64)__float_as_uint(v) << 32) | (u32)(1023 - p);
        sk[p] = ~key;
    }
    __syncthreads();
    for (int k = 2; k <= 1024; k <<= 1)
        for (int j = k >> 1; j > 0; j >>= 1) {
            for (int i2 = t; i2 < 1024; i2 += 512) {
                int l = i2 ^ j;
                if (l > i2) {
                    u64 a = sk[i2], bb = sk[l];
                    if ((a > bb) == ((i2 & k) == 0)) { sk[i2] = bb; sk[l] = a; }
                }
            }
            __syncthreads();
        }
    if (t < nk) {
        int p = 1023 - (int)((~sk[t]) & 0xFFFFFFFFu);
        g_sel[lvl][b][t] = p;
        out[xyOff + (b * nk + t) * 2] = (float)coords[p];
        out[xyOff + (b * nk + t) * 2 + 1] = (float)coords[1024 + p];
    }
}

__global__ void head_k(const int* __restrict__ coords, const float* __restrict__ hw,
                       const float* __restrict__ hb, float* __restrict__ out) {
    int lvl = blockIdx.z, b = blockIdx.y;
    int nk = (lvl == 0) ? 512 : ((lvl == 1) ? 256 : 128);
    int finOff = (lvl == 0) ? 65536 : ((lvl == 1) ? 94208 : 104448);
    int k = blockIdx.x * 4 + (threadIdx.x >> 5), lane = threadIdx.x & 31;
    if (k >= nk) return;
    int p = g_sel[lvl][b][k];
    int r = coords[p], c = coords[1024 + p];
    const float* af = g_px + (size_t)lvl * 1048576 + (size_t)(b * 1024 + r * 32 + c) * IC;
    float acc[4] = {0.f, 0.f, 0.f, 0.f};
#pragma unroll
    for (int q = 0; q < 2; q++) {
        float4 a4 = *(const float4*)(af + lane * 8 + q * 4);
#pragma unroll
        for (int j = 0; j < 4; j++) {
            float4 w4 = *(const float4*)(hw + j * IC + lane * 8 + q * 4);
            acc[j] += a4.x * w4.x + a4.y * w4.y + a4.z * w4.z + a4.w * w4.w;
        }
    }
#pragma unroll
    for (int o = 16; o; o >>= 1)
#pragma unroll
        for (int j = 0; j < 4; j++) acc[j] += __shfl_down_sync(0xffffffffu, acc[j], o);
    if (lane == 0) {
        float p0 = sigm(acc[0] + hb[0]), p1 = sigm(acc[1] + hb[1]);
        float p2 = sigm(acc[2] + hb[2]), p3 = sigm(acc[3] + hb[3]);
        *(float4*)(out + finOff + (size_t)(b * nk + k) * 4) =
            make_float4((float)r - 16.f * p0, (float)c - 16.f * p1, (float)r + 16.f * p2, (float)c + 16.f * p3);
    }
}

extern "C" void kernel_launch(void* const* d_in, const int* in_sizes, int n_in, void* d_out, int out_size) {
    const float* feat0 = (const float*)d_in[0];
    const float* feat1 = (const float*)d_in[1];
    const float* feat2 = (const float*)d_in[2];
    const int* coords = (const int*)d_in[3];
    const float* ehw = (const float*)d_in[22];
    const float* ehb = (const float*)d_in[23];
    const float* hw = (const float*)d_in[24];
    const float* hb = (const float*)d_in[25];
    float* out = (float*)d_out;
    PrepArgs P;
    for (int t = 0; t < 3; t++) {
        int base = 4 + 6 * t;
        P.w[t] = (const float*)d_in[base]; P.b[t] = (const float*)d_in[base + 1];
        P.g[t] = (const float*)d_in[base + 2]; P.bb[t] = (const float*)d_in[base + 3];
        P.m[t] = (const float*)d_in[base + 4]; P.v[t] = (const float*)d_in[base + 5];
    }
    int prepN = 9 * IC + 3 * IC * 9 * IC + 2 * 9 * 32768;
    prep_k<<<(prepN + 255) / 256, 256>>>(P);
    splitF_k<<<32768, 256>>>(feat0);
    dummy_k<<<1, 32>>>();
    mega_k<<<3064, 256>>>(feat0, feat1, feat2, ehw);
    em_k<<<(86016 + 255) / 256, 256>>>(ehb, out);
    sort_k<<<dim3(3, 4), 512>>>(coords, out, ehb, out);
    head_k<<<dim3(128, 4, 3), 128>>>(coords, hw, hb, out);
}

// round 16
// speedup vs baseline: 1.0947x; 1.0270x over previous
#include <cuda_runtime.h>
#include <cuda_bf16.h>
#include <math.h>
#define IC 256
typedef unsigned long long u64; typedef unsigned int u32;

__device__ __align__(256) float g_xs[22020096];
__device__ __align__(256) float g_px[3 * 1048576];
__device__ __align__(256) float g_part[2][86016];
__device__ __align__(256) float g_partx[8192];
__device__ __align__(256) float g_xc[1966080];
__device__ __align__(256) float g_wT[3][IC * 9 * IC];
__device__ __align__(256) float g_scale[3][3][IC];
__device__ __align__(256) float g_bias[3][3][IC];
__device__ int g_sel[3][4][512];
__device__ int g_cnt[4];
__device__ int g_rc[512];
__device__ __align__(256) u32 gF0b[2 * 8388608];
__device__ __align__(256) u32 gXsb[2 * 8388608];
__device__ __align__(256) u32 gWb[2 * 2 * 9 * 16 * 2048];

// FFMA2 stream (fi space, 1016): phaseA: share2, shareC0, share1 | phaseB: ent2, entC, ent1, pat2, pat1, pat0
__constant__ int f_st[10] = {0, 64, 184, 440, 504, 568, 824, 888, 952, 1016};
__constant__ int f_typ[9] = {0, 3, 0, 1, 4, 1, 2, 2, 2};
__constant__ int f_lvl[9] = {2, 0, 1, 2, 0, 1, 2, 1, 0};
__constant__ int f_tX[9]  = {2, 3, 4, 2, 2, 4, 2, 2, 2};
__constant__ int f_gi[9]  = {-1, -1, -1, 2, 3, 1, 2, 1, 0};
__constant__ int f_gn[9]  = {0, 0, 0, 64, 120, 256, 64, 256, 1024};

__device__ __forceinline__ u64 pack2(float v) {
    u64 d; unsigned r = __float_as_uint(v);
    asm("mov.b64 %0, {%1, %2};" : "=l"(d) : "r"(r), "r"(r)); return d;
}
__device__ __forceinline__ u64 ffma2(u64 a, u64 b, u64 c) {
    u64 d; asm("fma.rn.f32x2 %0, %1, %2, %3;" : "=l"(d) : "l"(a), "l"(b), "l"(c)); return d;
}
__device__ __forceinline__ void unpack2(u64 v, float& lo, float& hi) {
    unsigned a, b; asm("mov.b64 {%0, %1}, %2;" : "=r"(a), "=r"(b) : "l"(v));
    lo = __uint_as_float(a); hi = __uint_as_float(b);
}
__device__ __forceinline__ float sigm(float x) { return 1.f / (1.f + expf(-x)); }
__device__ __forceinline__ u32 bfpair(float lo, float hi) {
    __nv_bfloat162 h = __floats2bfloat162_rn(lo, hi);
    return *(u32*)&h;
}
__device__ __forceinline__ float bfres(float v) {
    return v - __bfloat162float(__float2bfloat16(v));
}
__device__ __forceinline__ void mmab(float* c, const u32* a, const u32* b) {
    asm volatile("mma.sync.aligned.m16n8k16.row.col.f32.bf16.bf16.f32 "
        "{%0,%1,%2,%3}, {%4,%5,%6,%7}, {%8,%9}, {%0,%1,%2,%3};"
        : "+f"(c[0]), "+f"(c[1]), "+f"(c[2]), "+f"(c[3])
        : "r"(a[0]), "r"(a[1]), "r"(a[2]), "r"(a[3]), "r"(b[0]), "r"(b[1]));
}

struct PrepArgs { const float *w[3], *b[3], *g[3], *bb[3], *m[3], *v[3]; };

__global__ void prep_k(PrepArgs P) {
    int idx = blockIdx.x * blockDim.x + threadIdx.x;
    if (idx < 4) g_cnt[idx] = 0;
    if (idx < 512) g_rc[idx] = 0;
    if (idx < 9 * IC) {
        int t = idx / (3 * IC), rem = idx % (3 * IC), l = rem / IC, ch = rem % IC;
        float s = P.g[t][l * IC + ch] / sqrtf(P.v[t][l * IC + ch] + 1e-5f);
        g_scale[t][l][ch] = s;
        g_bias[t][l][ch] = P.bb[t][l * IC + ch] + (P.b[t][ch] - P.m[t][l * IC + ch]) * s;
    }
    int j = idx - 9 * IC;
    if (j >= 0 && j < 3 * IC * 9 * IC) {
        int t = j / (IC * 9 * IC), rem = j % (IC * 9 * IC);
        int ci = rem / (9 * IC), tap = (rem / IC) % 9, n = rem % IC;
        g_wT[t][ci * 9 * IC + tap * IC + n] = P.w[t][n * IC * 9 + ci * 9 + tap];
    }
    int j2 = j - 3 * IC * 9 * IC;
    if (j2 >= 0 && j2 < 2 * 9 * 32768) {
        int t = j2 / (9 * 32768), rem = j2 % (9 * 32768);
        int tap = rem / 32768, r2 = rem % 32768;
        int c0p = r2 >> 11, cpl = (r2 >> 8) & 7, n = r2 & 255;
        int cp = c0p * 8 + cpl;
        float w0 = P.w[t][(n * 256 + 2 * cp) * 9 + tap];
        float w1 = P.w[t][(n * 256 + 2 * cp + 1) * 9 + tap];
        size_t o = ((size_t)((t * 2) * 9 + tap) * 16 + c0p) * 2048 + cpl * 256 + n;
        gWb[o] = bfpair(w0, w1);
        gWb[o + (size_t)9 * 32768] = bfpair(bfres(w0), bfres(w1));
    }
}

__global__ void splitF_k(const float* __restrict__ f0) {
    int i = blockIdx.x * blockDim.x + threadIdx.x;
    if (i >= 8388608) return;
    int b = i >> 21, rem = i & 2097151;
    int cp = rem >> 14, yx = rem & 16383;
    float v0 = f0[((size_t)(b * 256 + 2 * cp) * 16384) + yx];
    float v1 = f0[((size_t)(b * 256 + 2 * cp + 1) * 16384) + yx];
    size_t o = ((size_t)(b * 128 + cp) << 14) + yx;
    gF0b[o] = bfpair(v0, v1);
    gF0b[o + 8388608] = bfpair(bfres(v0), bfres(v1));
}

__global__ void dummy_k() {}

// exact FFMA2 conv body (verbatim)
__device__ __forceinline__ void ffmaConv(float* sBuf, int tid,
    const float* __restrict__ src, int srcH, int srcW, int y0, int x0,
    const float* __restrict__ wT, int nblk, const float* sc, const float* bi,
    int om, float* outX, int outW, int outPS, float* outPart, int partW,
    float* outPx, const float* __restrict__ ehw)
{
    float* sIn = sBuf; float* sW = sBuf + 1520;
    const int cg = tid >> 4, sg = tid & 15;
    const int srow = sg >> 1, sx = (sg & 1) * 8;
    u64 acc[4][8];
#pragma unroll
    for (int ii = 0; ii < 4; ii++)
#pragma unroll
        for (int j = 0; j < 8; j++) acc[ii][j] = 0ull;
    for (int c0 = 0; c0 < IC; c0 += 8) {
        for (int e = tid; e < 1520; e += 256) {
            int ci = e / 190, rem = e % 190, r = rem / 19, cc = rem % 19;
            int gy = y0 - 1 + r, gx = x0 - 1 + cc;
            float v = 0.f;
            if (cc < 18 && gy >= 0 && gy < srcH && gx >= 0 && gx < srcW)
                v = src[((size_t)(c0 + ci) * srcH + gy) * srcW + gx];
            sIn[e] = v;
        }
        for (int e4 = tid; e4 < 2304; e4 += 256) {
            int ci = e4 / 288, rem = e4 % 288, tap = rem / 32, n4 = rem % 32;
            float4 v = *(const float4*)(wT + (size_t)(c0 + ci) * (9 * IC) + tap * IC + nblk * 128 + n4 * 4);
            *(float4*)(sW + ci * 1152 + tap * 128 + n4 * 4) = v;
        }
        __syncthreads();
#pragma unroll 1
        for (int ci = 0; ci < 8; ci++) {
#pragma unroll
            for (int dy = 0; dy < 3; dy++) {
                const float* rp = sIn + ci * 190 + (srow + dy) * 19 + sx;
                u64 rr[10];
#pragma unroll
                for (int j = 0; j < 10; j++) rr[j] = pack2(rp[j]);
                const u64* wp = (const u64*)(sW + ci * 1152 + dy * 384 + cg * 8);
#pragma unroll
                for (int dx = 0; dx < 3; dx++) {
                    u64 w0 = wp[dx * 64], w1 = wp[dx * 64 + 1], w2 = wp[dx * 64 + 2], w3 = wp[dx * 64 + 3];
#pragma unroll
                    for (int m = 0; m < 8; m++) {
                        acc[0][m] = ffma2(w0, rr[m + dx], acc[0][m]);
                        acc[1][m] = ffma2(w1, rr[m + dx], acc[1][m]);
                        acc[2][m] = ffma2(w2, rr[m + dx], acc[2][m]);
                        acc[3][m] = ffma2(w3, rr[m + dx], acc[3][m]);
                    }
                }
            }
        }
        __syncthreads();
    }
    float psum[8];
#pragma unroll
    for (int m = 0; m < 8; m++) psum[m] = 0.f;
    const int y = y0 + srow, xb = x0 + sx;
#pragma unroll
    for (int n2 = 0; n2 < 4; n2++) {
        int cha = nblk * 128 + cg * 8 + 2 * n2, chb = cha + 1;
        float sa = sc[cha], ta = bi[cha], sb = sc[chb], tb = bi[chb];
        float va[8], vb[8];
#pragma unroll
        for (int m = 0; m < 8; m++) {
            float lo, hi; unpack2(acc[n2][m], lo, hi);
            va[m] = fmaxf(fmaf(lo, sa, ta), 0.f);
            vb[m] = fmaxf(fmaf(hi, sb, tb), 0.f);
        }
        if (om == 0) {
            float* oa = outX + (size_t)cha * outPS + y * outW + xb;
            float* ob = outX + (size_t)chb * outPS + y * outW + xb;
            *(float4*)(oa) = make_float4(va[0], va[1], va[2], va[3]);
            *(float4*)(oa + 4) = make_float4(va[4], va[5], va[6], va[7]);
            *(float4*)(ob) = make_float4(vb[0], vb[1], vb[2], vb[3]);
            *(float4*)(ob + 4) = make_float4(vb[4], vb[5], vb[6], vb[7]);
        } else if (om == 1) {
            float wa = ehw[cha], wb = ehw[chb];
#pragma unroll
            for (int m = 0; m < 8; m++) psum[m] += va[m] * wa + vb[m] * wb;
        } else {
#pragma unroll
            for (int m = 0; m < 8; m++) {
                float* o = outPx + (size_t)(y * 32 + xb + m) * IC;
                o[cha] = va[m]; o[chb] = vb[m];
            }
        }
    }
    if (om == 1) {
#pragma unroll
        for (int m = 0; m < 8; m++) sW[cg * 128 + srow * 16 + sx + m] = psum[m];
        __syncthreads();
        if (tid < 128) {
            float a2 = 0.f;
#pragma unroll
            for (int c2 = 0; c2 < 16; c2++) a2 += sW[c2 * 128 + tid];
            outPart[(y0 + (tid >> 4)) * partW + x0 + (tid & 15)] = a2;
        }
    }
}

__global__ __launch_bounds__(256, 2)
void mega_k(const float* __restrict__ f0, const float* __restrict__ f1,
            const float* __restrict__ f2, const float* __restrict__ ehw) {
    __shared__ __align__(16) float sBuf[10752];
    const int tid = threadIdx.x, wid = tid >> 5, lane = tid & 31;
    const int bid = blockIdx.x;

    // ---- phase-aware interleave: A = share0-tensor + ungated FFMA2; B = ent0-tensor + gated FFMA2
    int ti = -1, fi = -1;
    if (bid < 1464) {
        int g = bid / 183, r = bid - g * 183;
        if (r < 128) ti = g * 128 + r; else fi = g * 55 + (r - 128);
    } else {
        int bb = bid - 1464, g = bb / 200, r = bb - g * 200;
        if (r < 128) ti = 1024 + g * 128 + r; else fi = 440 + g * 72 + (r - 128);
    }

    if (ti >= 0) {
        // ===== bf16 2-split tensor conv lvl0 (verbatim R12 body, with reg prefetch) =====
        const int tw = (ti >= 1024), i = ti & 1023;
        const int y = i >> 3, b = (i >> 1) & 3, nblk = i & 1;
        const int wx = wid & 3, wy = wid >> 2;
        u32* S = (u32*)sBuf;
        if (tw == 1) {
            if (tid == 0) {
                int lo = y > 0 ? y - 1 : 0, hi = y < 127 ? y + 1 : 127; long long gd = 0;
                for (int rr = lo; rr <= hi; rr++)
                    while (atomicAdd(&g_rc[b * 128 + rr], 0) < 2 && gd < 400000000LL) gd++;
            }
            __syncthreads(); __threadfence();
        }
        const u32* __restrict__ plane = tw ? gXsb : gF0b;
        float acc[16][4];
#pragma unroll
        for (int q = 0; q < 16; q++) { acc[q][0] = acc[q][1] = acc[q][2] = acc[q][3] = 0.f; }
        if (tid < 128) {
            int s = tid >> 6, cpl = (tid >> 3) & 7, k = tid & 7;
            S[s * 1088 + cpl * 136 + 128 + k] = 0;
        }

        int dys[3]; int nd = 0;
#pragma unroll
        for (int dy = 0; dy < 3; dy++) { int iy = y + dy - 1; if (iy >= 0 && iy < 128) dys[nd++] = dy; }
        const int acl = tid >> 5, ax4 = (tid & 31) * 4;
        int bso[6], bsm[6];
#pragma unroll
        for (int k = 0; k < 6; k++) {
            int e = tid + 256 * k; int s = e >= 768; int r = e - s * 768;
            int dxk = r >> 8, rr = r & 255, cpl = rr >> 5, n4 = (rr & 31) * 4;
            bso[k] = (tw * 2 + s) * 9 + dxk;
            bsm[k] = 2176 + (s * 3 + dxk) * 1088 + cpl * 136 + n4;
            bso[k] = (bso[k] << 16) | (cpl * 256 + nblk * 128 + n4);
        }
        uint4 pa0, pa1, pb[6];
        const int total = nd * 16;
        {
            int iy = y + dys[0] - 1, c0p = 0;
            pa0 = *(const uint4*)(plane + ((((size_t)(0 * 4 + b) * 128 + c0p * 8 + acl) << 14) + iy * 128 + ax4));
            pa1 = *(const uint4*)(plane + ((((size_t)(1 * 4 + b) * 128 + c0p * 8 + acl) << 14) + iy * 128 + ax4));
#pragma unroll
            for (int k = 0; k < 6; k++) {
                int hi = bso[k] >> 16, lo2 = bso[k] & 0xFFFF;
                pb[k] = *(const uint4*)(gWb + ((size_t)(hi + dys[0] * 3) * 16 + c0p) * 2048 + lo2);
            }
        }
        for (int ci = 0; ci < total; ci++) {
            __syncthreads();
            *(uint4*)(S + acl * 136 + ax4) = pa0;
            *(uint4*)(S + 1088 + acl * 136 + ax4) = pa1;
#pragma unroll
            for (int k = 0; k < 6; k++) *(uint4*)(S + bsm[k]) = pb[k];
            __syncthreads();
            if (ci + 1 < total) {
                int cn = ci + 1, dyn_ = dys[cn >> 4], c0p = cn & 15;
                int iy = y + dyn_ - 1;
                pa0 = *(const uint4*)(plane + ((((size_t)(0 * 4 + b) * 128 + c0p * 8 + acl) << 14) + iy * 128 + ax4));
                pa1 = *(const uint4*)(plane + ((((size_t)(1 * 4 + b) * 128 + c0p * 8 + acl) << 14) + iy * 128 + ax4));
#pragma unroll
                for (int k = 0; k < 6; k++) {
                    int hi = bso[k] >> 16, lo2 = bso[k] & 0xFFFF;
                    pb[k] = *(const uint4*)(gWb + ((size_t)(hi + dyn_ * 3) * 16 + c0p) * 2048 + lo2);
                }
            }
#pragma unroll
            for (int dx = 0; dx < 3; dx++) {
                u32 a[2][2][4];
#pragma unroll
                for (int mf = 0; mf < 2; mf++) {
                    int px = wx * 32 + mf * 16 + (lane >> 2);
                    int g0 = px + dx - 1, g1 = g0 + 8;
                    int i0 = (g0 >= 0 && g0 < 128) ? g0 : 128;
                    int i1 = (g1 < 128) ? g1 : 128;
#pragma unroll
                    for (int s = 0; s < 2; s++) {
                        int base = s * 1088 + (lane & 3) * 136;
                        a[s][mf][0] = S[base + i0]; a[s][mf][1] = S[base + i1];
                        a[s][mf][2] = S[base + 544 + i0]; a[s][mf][3] = S[base + 544 + i1];
                    }
                }
#pragma unroll
                for (int nt = 0; nt < 8; nt++) {
                    int bb = 2176 + dx * 1088 + (lane & 3) * 136 + wy * 64 + nt * 8 + (lane >> 2);
                    u32 b0[2] = {S[bb], S[bb + 544]};
                    u32 b1[2] = {S[bb + 3264], S[bb + 3264 + 544]};
#pragma unroll
                    for (int mf = 0; mf < 2; mf++) {
                        mmab(acc[mf * 8 + nt], a[0][mf], b0);
                        mmab(acc[mf * 8 + nt], a[0][mf], b1);
                        mmab(acc[mf * 8 + nt], a[1][mf], b0);
                    }
                }
            }
        }
        const float* sc = g_scale[tw][0]; const float* bi = g_bias[tw][0];
        float psum[4] = {0.f, 0.f, 0.f, 0.f};
#pragma unroll
        for (int mf = 0; mf < 2; mf++)
#pragma unroll
            for (int nt = 0; nt < 8; nt++)
#pragma unroll
                for (int h = 0; h < 2; h++) {
                    int px = wx * 32 + mf * 16 + (lane >> 2) + h * 8;
                    int ch0 = nblk * 128 + wy * 64 + nt * 8 + (lane & 3) * 2;
                    float v0 = fmaxf(fmaf(acc[mf * 8 + nt][h * 2], sc[ch0], bi[ch0]), 0.f);
                    float v1 = fmaxf(fmaf(acc[mf * 8 + nt][h * 2 + 1], sc[ch0 + 1], bi[ch0 + 1]), 0.f);
                    if (tw == 0) {
                        size_t o = ((size_t)(b * 256 + ch0) * 128 + y) * 128 + px;
                        g_xs[o] = v0; g_xs[o + 16384] = v1;
                        size_t ob = (((size_t)b * 128 + (ch0 >> 1)) << 14) + y * 128 + px;
                        gXsb[ob] = bfpair(v0, v1);
                        gXsb[ob + 8388608] = bfpair(bfres(v0), bfres(v1));
                    } else psum[mf * 2 + h] += v0 * ehw[ch0] + v1 * ehw[ch0 + 1];
                }
        if (tw == 1) {
#pragma unroll
            for (int q = 0; q < 4; q++) {
                psum[q] += __shfl_xor_sync(0xffffffffu, psum[q], 1);
                psum[q] += __shfl_xor_sync(0xffffffffu, psum[q], 2);
            }
            __syncthreads();
            if ((lane & 3) == 0)
#pragma unroll
                for (int q = 0; q < 4; q++)
                    sBuf[wy * 128 + wx * 32 + (q & 1) * 8 + (q >> 1) * 16 + (lane >> 2)] = psum[q];
            __syncthreads();
            if (tid < 128) g_part[nblk][b * 16384 + y * 128 + tid] = sBuf[tid] + sBuf[128 + tid];
        } else {
            __threadfence(); __syncthreads();
            if (tid == 0) { atomicAdd(&g_rc[b * 128 + y], 1); atomicAdd(&g_cnt[0], 1); }
        }
        return;
    }

    // ===== FFMA2 segments (fi space; bodies verbatim) =====
    int s = 0; while (s < 9 && !(fi >= f_st[s] && fi < f_st[s + 1])) s++;
    const int typ = f_typ[s], lvl = f_lvl[s], tX = f_tX[s];
    const int i = fi - f_st[s];
    const int tile = i >> 3, b = (i >> 1) & 3, nblk = i & 1;
    const int y0 = (tile / tX) * 8, x0 = (tile % tX) * 16;
    if (f_gi[s] >= 0) {
        if (tid == 0) {
            long long gd = 0;
            while (atomicAdd(&g_cnt[f_gi[s]], 0) < f_gn[s] && gd < 400000000LL) gd++;
        }
        __syncthreads(); __threadfence();
    }
    const int Hs = (lvl == 0) ? 128 : ((lvl == 1) ? 64 : 32);
    const size_t xsoff = (lvl == 0) ? 0ul : ((lvl == 1) ? 16777216ul : 20971520ul);
    int tower = (typ == 0 || typ == 3) ? 0 : ((typ == 1 || typ == 4) ? 1 : 2);
    const float* sc = g_scale[tower][lvl];
    const float* bi = g_bias[tower][lvl];
    const float* wT = g_wT[tower];

    if (typ == 3) {
        ffmaConv(sBuf, tid, f0 + (size_t)b * IC * 16384, 128, 128, y0, x0, wT, nblk, sc, bi,
                 0, g_xc + (size_t)b * IC * 1920, 48, 1920, nullptr, 0, nullptr, ehw);
        __threadfence(); __syncthreads();
        if (tid == 0) atomicAdd(&g_cnt[3], 1);
    } else if (typ == 0) {
        const float* src = ((lvl == 1) ? f1 : f2) + (size_t)b * IC * Hs * Hs;
        ffmaConv(sBuf, tid, src, Hs, Hs, y0, x0, wT, nblk, sc, bi,
                 0, g_xs + xsoff + (size_t)b * IC * Hs * Hs, Hs, Hs * Hs, nullptr, 0, nullptr, ehw);
        __threadfence(); __syncthreads();
        if (tid == 0) atomicAdd(&g_cnt[lvl], 1);
    } else if (typ == 4) {
        ffmaConv(sBuf, tid, g_xc + (size_t)b * IC * 1920, 40, 48, y0, x0, wT, nblk, sc, bi,
                 1, nullptr, 0, 0, g_partx + nblk * 4096 + b * 1024, 32, nullptr, ehw);
    } else if (typ == 1) {
        int po = (lvl == 1) ? 65536 : 81920;
        ffmaConv(sBuf, tid, g_xs + xsoff + (size_t)b * IC * Hs * Hs, Hs, Hs, y0, x0, wT, nblk, sc, bi,
                 1, nullptr, 0, 0, g_part[nblk] + po + b * Hs * Hs, Hs, nullptr, ehw);
    } else {
        ffmaConv(sBuf, tid, g_xs + xsoff + (size_t)b * IC * Hs * Hs, Hs, Hs, y0, x0, wT, nblk, sc, bi,
                 2, nullptr, 0, 0, nullptr, 0, g_px + (size_t)lvl * 1048576 + (size_t)b * 1024 * IC, ehw);
    }
}

__global__ void em_k(const float* __restrict__ ehb, float* __restrict__ out) {
    int i = blockIdx.x * blockDim.x + threadIdx.x;
    if (i >= 86016) return;
    int emo = (i < 65536) ? 0 : ((i < 81920) ? 77824 - 65536 : 100352 - 81920);
    out[emo + i] = sigm(g_part[0][i] + g_part[1][i] + ehb[0]);
}

__global__ void sort_k(const int* __restrict__ coords, const float* __restrict__ base,
                       const float* __restrict__ ehb, float* __restrict__ out) {
    __shared__ u64 sk[1024];
    int lvl = blockIdx.x, b = blockIdx.y, t = threadIdx.x;
    int H = (lvl == 0) ? 128 : ((lvl == 1) ? 64 : 32);
    int nk = (lvl == 0) ? 512 : ((lvl == 1) ? 256 : 128);
    int emOff = (lvl == 0) ? 0 : ((lvl == 1) ? 77824 : 100352);
    int xyOff = (lvl == 0) ? 73728 : ((lvl == 1) ? 98304 : 106496);
    const float* em = base + emOff + b * H * H;
    for (int p = t; p < 1024; p += 512) {
        int r = coords[p], c = coords[1024 + p];
        float v = (lvl == 0) ? sigm(g_partx[b * 1024 + r * 32 + c] + g_partx[4096 + b * 1024 + r * 32 + c] + ehb[0])
                             : em[r * H + c];
        u64 key = ((u64)__float_as_uint(v) << 32) | (u32)(1023 - p);
        sk[p] = ~key;
    }
    __syncthreads();
    for (int k = 2; k <= 1024; k <<= 1)
        for (int j = k >> 1; j > 0; j >>= 1) {
            for (int i2 = t; i2 < 1024; i2 += 512) {
                int l = i2 ^ j;
                if (l > i2) {
                    u64 a = sk[i2], bb = sk[l];
                    if ((a > bb) == ((i2 & k) == 0)) { sk[i2] = bb; sk[l] = a; }
                }
            }
            __syncthreads();
        }
    if (t < nk) {
        int p = 1023 - (int)((~sk[t]) & 0xFFFFFFFFu);
        g_sel[lvl][b][t] = p;
        out[xyOff + (b * nk + t) * 2] = (float)coords[p];
        out[xyOff + (b * nk + t) * 2 + 1] = (float)coords[1024 + p];
    }
}

__global__ void head_k(const int* __restrict__ coords, const float* __restrict__ hw,
                       const float* __restrict__ hb, float* __restrict__ out) {
    int lvl = blockIdx.z, b = blockIdx.y;
    int nk = (lvl == 0) ? 512 : ((lvl == 1) ? 256 : 128);
    int finOff = (lvl == 0) ? 65536 : ((lvl == 1) ? 94208 : 104448);
    int k = blockIdx.x * 4 + (threadIdx.x >> 5), lane = threadIdx.x & 31;
    if (k >= nk) return;
    int p = g_sel[lvl][b][k];
    int r = coords[p], c = coords[1024 + p];
    const float* af = g_px + (size_t)lvl * 1048576 + (size_t)(b * 1024 + r * 32 + c) * IC;
    float acc[4] = {0.f, 0.f, 0.f, 0.f};
#pragma unroll
    for (int q = 0; q < 2; q++) {
        float4 a4 = *(const float4*)(af + lane * 8 + q * 4);
#pragma unroll
        for (int j = 0; j < 4; j++) {
            float4 w4 = *(const float4*)(hw + j * IC + lane * 8 + q * 4);
            acc[j] += a4.x * w4.x + a4.y * w4.y + a4.z * w4.z + a4.w * w4.w;
        }
    }
#pragma unroll
    for (int o = 16; o; o >>= 1)
#pragma unroll
        for (int j = 0; j < 4; j++) acc[j] += __shfl_down_sync(0xffffffffu, acc[j], o);
    if (lane == 0) {
        float p0 = sigm(acc[0] + hb[0]), p1 = sigm(acc[1] + hb[1]);
        float p2 = sigm(acc[2] + hb[2]), p3 = sigm(acc[3] + hb[3]);
        *(float4*)(out + finOff + (size_t)(b * nk + k) * 4) =
            make_float4((float)r - 16.f * p0, (float)c - 16.f * p1, (float)r + 16.f * p2, (float)c + 16.f * p3);
    }
}

extern "C" void kernel_launch(void* const* d_in, const int* in_sizes, int n_in, void* d_out, int out_size) {
    const float* feat0 = (const float*)d_in[0];
    const float* feat1 = (const float*)d_in[1];
    const float* feat2 = (const float*)d_in[2];
    const int* coords = (const int*)d_in[3];
    const float* ehw = (const float*)d_in[22];
    const float* ehb = (const float*)d_in[23];
    const float* hw = (const float*)d_in[24];
    const float* hb = (const float*)d_in[25];
    float* out = (float*)d_out;
    PrepArgs P;
    for (int t = 0; t < 3; t++) {
        int base = 4 + 6 * t;
        P.w[t] = (const float*)d_in[base]; P.b[t] = (const float*)d_in[base + 1];
        P.g[t] = (const float*)d_in[base + 2]; P.bb[t] = (const float*)d_in[base + 3];
        P.m[t] = (const float*)d_in[base + 4]; P.v[t] = (const float*)d_in[base + 5];
    }
    int prepN = 9 * IC + 3 * IC * 9 * IC + 2 * 9 * 32768;
    prep_k<<<(prepN + 255) / 256, 256>>>(P);
    splitF_k<<<32768, 256>>>(feat0);
    dummy_k<<<1, 32>>>();
    mega_k<<<3064, 256>>>(feat0, feat1, feat2, ehw);
    em_k<<<(86016 + 255) / 256, 256>>>(ehb, out);
    sort_k<<<dim3(3, 4), 512>>>(coords, out, ehb, out);
    head_k<<<dim3(128, 4, 3), 128>>>(coords, hw, hb, out);
}